// round 6
// baseline (speedup 1.0000x reference)
#include <cuda_runtime.h>
#include <cuda_bf16.h>
#include <math.h>
#include <stdint.h>

namespace {
constexpr int NB = 4, TE = 256, TD = 512, DM = 512, DI = 1024, DS = 16, DTR = 32, NM = 80;
constexpr int ME = NB * TE;   // 1024 encoder rows
constexpr int MD = NB * TD;   // 2048 decoder rows
constexpr int KS = 8;         // xproj split-K factor
constexpr int PITCH = 40;     // smem halves per row (80B) -> conflict-free ldmatrix
}

// ---------------- scratch ----------------
__device__ float g_x0[MD * DM];
__device__ float g_x1[MD * DM];
__device__ float g_xz[MD * 2 * DI];
__device__ float g_u[MD * DI];
__device__ float g_xdbl[MD * 64];
__device__ float g_part[KS * MD * 64];
__device__ float g_delta[MD * DI];
__device__ float g_gate[MD * DI];
__device__ float g_im2col[ME * DM * 3];
__device__ float g_wt[DM * 3 * DM];
__device__ float g_h1[ME * DM];
__device__ float g_h2[ME * DM];
__device__ float g_dur[ME];
__device__ int   g_idx[NB * TD];
__device__ float g_mask[NB * TD];
__device__ uint4 g_aext[786432];   // 6291456 bf16 >= 2048*3072
__device__ uint4 g_wext[393216];   // 3145728 bf16 >= max(2048*1536, 512*4608)

__device__ __forceinline__ float softplus_f(float x) {
    return x > 0.f ? x + log1pf(expf(-x)) : log1pf(expf(x));
}
__device__ __forceinline__ float silu_f(float x) {
    return x / (1.f + expf(-x));
}
__device__ __forceinline__ uint32_t smem_u32(const void* p) {
    uint32_t a;
    asm("{ .reg .u64 t; cvta.to.shared.u64 t, %1; cvt.u32.u64 %0, t; }" : "=r"(a) : "l"(p));
    return a;
}

// ================= split-bf16 conversion kernels =================
// Aext row m: [hi | hi | lo]  (bf16, 3K per row)
__global__ void split_a_k(const float* __restrict__ A, __nv_bfloat16* __restrict__ out,
                          int MK, int K) {
    int i = blockIdx.x * blockDim.x + threadIdx.x;
    if (i >= MK) return;
    int m = i / K, k = i % K;
    float a = A[i];
    __nv_bfloat16 hi = __float2bfloat16_rn(a);
    __nv_bfloat16 lo = __float2bfloat16_rn(a - __bfloat162float(hi));
    size_t base = (size_t)m * 3 * K;
    out[base + k] = hi;
    out[base + K + k] = hi;
    out[base + 2 * K + k] = lo;
}
// W [K,N] f32 -> Wext [N,3K] bf16, row n: [hi | lo | hi]  (transpose via smem)
__global__ void split_w_k(const float* __restrict__ W, __nv_bfloat16* __restrict__ out,
                          int K, int N) {
    __shared__ float tile[32][33];
    int n0 = blockIdx.x * 32, k0 = blockIdx.y * 32;
    int tx = threadIdx.x, ty = threadIdx.y;
    tile[ty][tx] = W[(size_t)(k0 + ty) * N + n0 + tx];
    __syncthreads();
    int n = n0 + ty, k = k0 + tx;
    float a = tile[tx][ty];
    __nv_bfloat16 hi = __float2bfloat16_rn(a);
    __nv_bfloat16 lo = __float2bfloat16_rn(a - __bfloat162float(hi));
    size_t base = (size_t)n * 3 * K;
    out[base + k] = hi;
    out[base + K + k] = lo;
    out[base + 2 * K + k] = hi;
}

// ================= HMMA bf16 GEMM: C[M,N] = Aext[M,K3] @ Bext[N,K3]^T =================
// 128x128 block, BK=32, 8 warps (2x4), warp tile 64x32, mma.m16n8k16, double-buffered.
// EPI: 0=none, 2=relu(+bias)*bn_scale+bn_shift
template<int EPI>
__global__ __launch_bounds__(256) void hmma_k(
    const __nv_bfloat16* __restrict__ Ae, const __nv_bfloat16* __restrict__ Be,
    float* __restrict__ C, int K3, int N,
    const float* __restrict__ bias, const float* __restrict__ gamma,
    const float* __restrict__ beta)
{
    __shared__ __align__(16) __nv_bfloat16 sA[2][128 * PITCH];
    __shared__ __align__(16) __nv_bfloat16 sB[2][128 * PITCH];

    const int tid = threadIdx.x, lane = tid & 31, w = tid >> 5;
    const int wm = w & 1, wn = w >> 1;              // 2 x 4 warp grid
    const int bm = blockIdx.y * 128, bn = blockIdx.x * 128;
    const size_t arow = (size_t)K3 * 2;             // bytes per ext row

    const char* Ag = (const char*)Ae + (size_t)bm * arow;
    const char* Bg = (const char*)Be + (size_t)bn * arow;
    const int ldr = tid >> 2, lds = tid & 3;        // 128 rows x 4 x 16B segs

    uint4 ar1, ar2, br1, br2;
    auto g2r_full = [&](int kc) {
        size_t o1 = (size_t)ldr * arow + (size_t)kc * 64 + lds * 16;
        size_t o2 = (size_t)(ldr + 64) * arow + (size_t)kc * 64 + lds * 16;
        ar1 = *reinterpret_cast<const uint4*>(Ag + o1);
        ar2 = *reinterpret_cast<const uint4*>(Ag + o2);
        br1 = *reinterpret_cast<const uint4*>(Bg + o1);
        br2 = *reinterpret_cast<const uint4*>(Bg + o2);
    };
    auto r2s = [&](int b) {
        char* pa = (char*)sA[b];
        char* pb = (char*)sB[b];
        *reinterpret_cast<uint4*>(pa + ldr * (PITCH * 2) + lds * 16) = ar1;
        *reinterpret_cast<uint4*>(pa + (ldr + 64) * (PITCH * 2) + lds * 16) = ar2;
        *reinterpret_cast<uint4*>(pb + ldr * (PITCH * 2) + lds * 16) = br1;
        *reinterpret_cast<uint4*>(pb + (ldr + 64) * (PITCH * 2) + lds * 16) = br2;
    };

    float acc[4][4][4] = {};

    // ldmatrix lane addressing
    const int a_row = wm * 64 + (lane & 15);        // + mt*16
    const int a_kof = (lane >> 4) * 8;              // + ks*16
    const int bl = lane & 15;
    const int b_row = wn * 32 + (bl & 7);           // + nt*8
    const int b_kof = (bl >> 3) * 8;                // + ks*16

    auto compute = [&](int b) {
        const uint32_t abase = smem_u32(sA[b]);
        const uint32_t bbase = smem_u32(sB[b]);
        #pragma unroll
        for (int ks = 0; ks < 2; ks++) {
            uint32_t af[4][4];
            #pragma unroll
            for (int mt = 0; mt < 4; mt++) {
                uint32_t addr = abase + (a_row + mt * 16) * (PITCH * 2) + (a_kof + ks * 16) * 2;
                asm volatile("ldmatrix.sync.aligned.m8n8.x4.shared.b16 {%0,%1,%2,%3}, [%4];"
                    : "=r"(af[mt][0]), "=r"(af[mt][1]), "=r"(af[mt][2]), "=r"(af[mt][3])
                    : "r"(addr));
            }
            uint32_t bf[4][2];
            #pragma unroll
            for (int nt = 0; nt < 4; nt++) {
                uint32_t addr = bbase + (b_row + nt * 8) * (PITCH * 2) + (b_kof + ks * 16) * 2;
                asm volatile("ldmatrix.sync.aligned.m8n8.x2.shared.b16 {%0,%1}, [%2];"
                    : "=r"(bf[nt][0]), "=r"(bf[nt][1])
                    : "r"(addr));
            }
            #pragma unroll
            for (int mt = 0; mt < 4; mt++)
                #pragma unroll
                for (int nt = 0; nt < 4; nt++) {
                    asm volatile(
                        "mma.sync.aligned.m16n8k16.row.col.f32.bf16.bf16.f32 "
                        "{%0,%1,%2,%3}, {%4,%5,%6,%7}, {%8,%9}, {%0,%1,%2,%3};"
                        : "+f"(acc[mt][nt][0]), "+f"(acc[mt][nt][1]),
                          "+f"(acc[mt][nt][2]), "+f"(acc[mt][nt][3])
                        : "r"(af[mt][0]), "r"(af[mt][1]), "r"(af[mt][2]), "r"(af[mt][3]),
                          "r"(bf[nt][0]), "r"(bf[nt][1]));
                }
        }
    };

    const int NC = K3 / 32;
    g2r_full(0); r2s(0); __syncthreads();
    for (int kc = 0; kc < NC; kc++) {
        const int cur = kc & 1;
        if (kc + 1 < NC) g2r_full(kc + 1);
        compute(cur);
        if (kc + 1 < NC) r2s(1 - cur);
        __syncthreads();
    }

    // epilogue: C fragments -> global (float2 stores)
    const int tq = lane >> 2, tr = lane & 3;
    #pragma unroll
    for (int mt = 0; mt < 4; mt++) {
        #pragma unroll
        for (int nt = 0; nt < 4; nt++) {
            int row0 = bm + wm * 64 + mt * 16 + tq;
            int col = bn + wn * 32 + nt * 8 + tr * 2;
            float v[4] = {acc[mt][nt][0], acc[mt][nt][1], acc[mt][nt][2], acc[mt][nt][3]};
            if (EPI == 2) {
                #pragma unroll
                for (int e = 0; e < 4; e++) {
                    int n = col + (e & 1);
                    v[e] = fmaxf(v[e] + bias[n], 0.f) * (gamma[n] * rsqrtf(1.f + 1e-5f)) + beta[n];
                }
            }
            *reinterpret_cast<float2*>(C + (size_t)row0 * N + col) = make_float2(v[0], v[1]);
            *reinterpret_cast<float2*>(C + (size_t)(row0 + 8) * N + col) = make_float2(v[2], v[3]);
        }
    }
}

// ---------------- embedding ----------------
__global__ void embed_k(const int* __restrict__ text, const float* __restrict__ emb,
                        float* __restrict__ out) {
    int i = blockIdx.x * blockDim.x + threadIdx.x;
    if (i >= ME * DM) return;
    int c = i % DM;
    int r = i / DM;
    out[i] = emb[text[r] * DM + c];
}

// ============ gemm64 (fp32): used only for dt projection (K=32) ============
template<int EPI>
__global__ __launch_bounds__(256) void gemm64_k(
    const float* __restrict__ A, const float* __restrict__ W, float* __restrict__ C,
    int K, int lda, int ldb, int ldc,
    const float* __restrict__ bias, const float* __restrict__ gamma,
    const float* __restrict__ beta)
{
    __shared__ float As[2][16][64];
    __shared__ float Bs[2][16][64];
    const int tid = threadIdx.x;
    const int tx = tid & 15, ty = tid >> 4;
    const int bm = blockIdx.y * 64, bn = blockIdx.x * 64;
    const int ar = tid >> 2, ac = (tid & 3) << 2;
    const int br = tid >> 4, bc = (tid & 15) << 2;
    const float* Ag = A + (size_t)(bm + ar) * lda + ac;
    const float* Wg = W + bn + bc;

    float4 ap, bp;
    auto ld = [&](int k0) {
        ap = *reinterpret_cast<const float4*>(Ag + k0);
        bp = *reinterpret_cast<const float4*>(Wg + (size_t)(k0 + br) * ldb);
    };
    auto st = [&](int buf) {
        As[buf][ac + 0][ar] = ap.x; As[buf][ac + 1][ar] = ap.y;
        As[buf][ac + 2][ar] = ap.z; As[buf][ac + 3][ar] = ap.w;
        *reinterpret_cast<float4*>(&Bs[buf][br][bc]) = bp;
    };

    float acc[4][4] = {};
    const int KB = K / 16;
    ld(0); st(0); __syncthreads();
    for (int kb = 0; kb < KB; kb++) {
        const int cur = kb & 1;
        if (kb + 1 < KB) ld((kb + 1) * 16);
        #pragma unroll
        for (int kk = 0; kk < 16; kk++) {
            float a[4], b[4];
            *reinterpret_cast<float4*>(a) = *reinterpret_cast<const float4*>(&As[cur][kk][ty * 4]);
            *reinterpret_cast<float4*>(b) = *reinterpret_cast<const float4*>(&Bs[cur][kk][tx * 4]);
            #pragma unroll
            for (int i = 0; i < 4; i++)
                #pragma unroll
                for (int j = 0; j < 4; j++)
                    acc[i][j] = fmaf(a[i], b[j], acc[i][j]);
        }
        if (kb + 1 < KB) st(1 - cur);
        __syncthreads();
    }
    #pragma unroll
    for (int i = 0; i < 4; i++) {
        const int m = bm + ty * 4 + i;
        const int n0 = bn + tx * 4;
        float4 v;
        float* pv = &v.x;
        #pragma unroll
        for (int q = 0; q < 4; q++) {
            float x = acc[i][q];
            if (EPI == 1) x = softplus_f(x + bias[n0 + q]);
            else if (EPI == 2)
                x = fmaxf(x + bias[n0 + q], 0.f) * (gamma[n0 + q] * rsqrtf(1.f + 1e-5f)) + beta[n0 + q];
            pv[q] = x;
        }
        *reinterpret_cast<float4*>(C + (size_t)m * ldc + n0) = v;
    }
}

// ============ xproj split-K (fp32) ============
__global__ __launch_bounds__(256) void xp_k(
    const float* __restrict__ A, const float* __restrict__ W, float* __restrict__ P, int M)
{
    __shared__ float As[2][16][64];
    __shared__ float Bs[2][16][64];
    const int tid = threadIdx.x;
    const int tx = tid & 15, ty = tid >> 4;
    const int bm = blockIdx.x * 64;
    const int kz = blockIdx.y;
    const int kbase = kz * (DI / KS);
    const int ar = tid >> 2, ac = (tid & 3) << 2;
    const int br = tid >> 4, bc = (tid & 15) << 2;
    const float* Ag = A + (size_t)(bm + ar) * DI + kbase + ac;
    const float* Wg = W + (size_t)kbase * 64 + bc;

    float4 ap, bp;
    auto ld = [&](int k0) {
        ap = *reinterpret_cast<const float4*>(Ag + k0);
        bp = *reinterpret_cast<const float4*>(Wg + (size_t)(k0 + br) * 64);
    };
    auto st = [&](int buf) {
        As[buf][ac + 0][ar] = ap.x; As[buf][ac + 1][ar] = ap.y;
        As[buf][ac + 2][ar] = ap.z; As[buf][ac + 3][ar] = ap.w;
        *reinterpret_cast<float4*>(&Bs[buf][br][bc]) = bp;
    };

    float acc[4][4] = {};
    const int KB = (DI / KS) / 16;
    ld(0); st(0); __syncthreads();
    for (int kb = 0; kb < KB; kb++) {
        const int cur = kb & 1;
        if (kb + 1 < KB) ld((kb + 1) * 16);
        #pragma unroll
        for (int kk = 0; kk < 16; kk++) {
            float a[4], b[4];
            *reinterpret_cast<float4*>(a) = *reinterpret_cast<const float4*>(&As[cur][kk][ty * 4]);
            *reinterpret_cast<float4*>(b) = *reinterpret_cast<const float4*>(&Bs[cur][kk][tx * 4]);
            #pragma unroll
            for (int i = 0; i < 4; i++)
                #pragma unroll
                for (int j = 0; j < 4; j++)
                    acc[i][j] = fmaf(a[i], b[j], acc[i][j]);
        }
        if (kb + 1 < KB) st(1 - cur);
        __syncthreads();
    }
    float* Pg = P + ((size_t)kz * M + bm) * 64;
    #pragma unroll
    for (int i = 0; i < 4; i++) {
        float4 v = make_float4(acc[i][0], acc[i][1], acc[i][2], acc[i][3]);
        *reinterpret_cast<float4*>(Pg + (size_t)(ty * 4 + i) * 64 + tx * 4) = v;
    }
}

__global__ void xp_reduce_k(const float* __restrict__ P, float* __restrict__ out, int M) {
    int i = blockIdx.x * blockDim.x + threadIdx.x;
    if (i >= M * 16) return;
    float4 s = make_float4(0.f, 0.f, 0.f, 0.f);
    #pragma unroll
    for (int z = 0; z < KS; z++) {
        float4 v = *reinterpret_cast<const float4*>(P + ((size_t)z * M * 16 + i) * 4);
        s.x += v.x; s.y += v.y; s.z += v.z; s.w += v.w;
    }
    *reinterpret_cast<float4*>(out + (size_t)i * 4) = s;
}

// ---------------- depthwise causal conv (K=4) + SiLU ----------------
__global__ void dwconv_silu_k(const float* __restrict__ xz, const float* __restrict__ w,
                              const float* __restrict__ bcv, float* __restrict__ u, int L) {
    int i = blockIdx.x * blockDim.x + threadIdx.x;
    int total = NB * L * DI;
    if (i >= total) return;
    int d = i % DI;
    int bt = i / DI;
    int t = bt % L;
    int bb = bt / L;
    float acc = bcv[d];
    const float* wr = w + d * 4;
    #pragma unroll
    for (int k = 0; k < 4; k++) {
        int ts = t - 3 + k;
        if (ts >= 0)
            acc = fmaf(wr[k], xz[((size_t)(bb * L + ts)) * 2048 + d], acc);
    }
    u[i] = silu_f(acc);
}

// ---------------- selective scan with next-step prefetch ----------------
__global__ void scan_k(const float* __restrict__ xdbl, const float* __restrict__ delta,
                       const float* __restrict__ u, const float* __restrict__ xz,
                       const float* __restrict__ Alog, const float* __restrict__ Dp,
                       float* __restrict__ gate, int L) {
    int gt = blockIdx.x * blockDim.x + threadIdx.x;
    if (gt >= NB * DI * 4) return;
    int lane = gt & 3;
    int gid = gt >> 2;
    int d = gid % DI;
    int bb = gid / DI;
    float a0 = -expf(Alog[d * DS + lane * 4 + 0]);
    float a1 = -expf(Alog[d * DS + lane * 4 + 1]);
    float a2 = -expf(Alog[d * DS + lane * 4 + 2]);
    float a3 = -expf(Alog[d * DS + lane * 4 + 3]);
    float Dd = Dp[d];
    float h0 = 0.f, h1 = 0.f, h2 = 0.f, h3 = 0.f;

    float dl, ut, rs;
    float4 Bv, Cv;
    auto loadt = [&](int t, float& dl_, float& ut_, float4& B_, float4& C_, float& rs_) {
        size_t row = (size_t)bb * L + t;
        dl_ = delta[row * DI + d];
        ut_ = u[row * DI + d];
        const float* xd = xdbl + row * 64;
        B_ = *reinterpret_cast<const float4*>(xd + 32 + lane * 4);
        C_ = *reinterpret_cast<const float4*>(xd + 48 + lane * 4);
        rs_ = xz[row * 2048 + 1024 + d];
    };
    loadt(0, dl, ut, Bv, Cv, rs);
    for (int t = 0; t < L; t++) {
        float dl2, ut2, rs2;
        float4 Bv2, Cv2;
        if (t + 1 < L) loadt(t + 1, dl2, ut2, Bv2, Cv2, rs2);
        float du = dl * ut;
        h0 = fmaf(__expf(dl * a0), h0, du * Bv.x);
        h1 = fmaf(__expf(dl * a1), h1, du * Bv.y);
        h2 = fmaf(__expf(dl * a2), h2, du * Bv.z);
        h3 = fmaf(__expf(dl * a3), h3, du * Bv.w);
        float y = h0 * Cv.x + h1 * Cv.y + h2 * Cv.z + h3 * Cv.w;
        y += __shfl_xor_sync(0xffffffffu, y, 1);
        y += __shfl_xor_sync(0xffffffffu, y, 2);
        if (lane == 0) {
            size_t row = (size_t)bb * L + t;
            gate[row * DI + d] = (y + ut * Dd) * silu_f(rs);
        }
        dl = dl2; ut = ut2; Bv = Bv2; Cv = Cv2; rs = rs2;
    }
}

// ---------------- duration predictor helpers ----------------
__global__ void wt_k(const float* __restrict__ w, float* __restrict__ wt) {
    int i = blockIdx.x * blockDim.x + threadIdx.x;
    if (i >= DM * DM * 3) return;
    int k = i % 3;
    int c = (i / 3) % DM;
    int d = i / (3 * DM);
    wt[(size_t)(k * DM + c) * DM + d] = w[i];
}
__global__ void im2col_k(const float* __restrict__ src, float* __restrict__ dst) {
    int i = blockIdx.x * blockDim.x + threadIdx.x;
    if (i >= ME * DM * 3) return;
    int c = i % DM;
    int k = (i / DM) % 3;
    int r = i / (DM * 3);
    int t = r % TE;
    int ts = t - 1 + k;
    float v = 0.f;
    if (ts >= 0 && ts < TE) v = src[(size_t)(r - t + ts) * DM + c];
    dst[i] = v;
}
__global__ void dur_k(const float* __restrict__ h2, const float* __restrict__ w3,
                      const float* __restrict__ b3, float* __restrict__ dur) {
    int warp = (blockIdx.x * blockDim.x + threadIdx.x) >> 5;
    int lane = threadIdx.x & 31;
    if (warp >= ME) return;
    const float* hr = h2 + (size_t)warp * DM;
    float s = 0.f;
    for (int c = lane; c < DM; c += 32) s = fmaf(hr[c], w3[c], s);
    #pragma unroll
    for (int o = 16; o; o >>= 1) s += __shfl_xor_sync(0xffffffffu, s, o);
    if (lane == 0) dur[warp] = softplus_f(s + b3[0]);
}

// ---------------- length regulator ----------------
__global__ void expand_k(const float* __restrict__ dur, int* __restrict__ idx,
                         float* __restrict__ mask) {
    __shared__ float ends[TE];
    int bb = blockIdx.x;
    int t = threadIdx.x;
    ends[t] = rintf(fmaxf(dur[bb * TE + t], 0.f));
    __syncthreads();
    if (t == 0) {
        float s = 0.f;
        for (int i = 0; i < TE; i++) { s += ends[i]; ends[i] = s; }
    }
    __syncthreads();
    float total = ends[TE - 1];
    for (int tp = t; tp < TD; tp += TE) {
        float fp = (float)tp;
        int lo = 0, hi = TE;
        while (lo < hi) { int mid = (lo + hi) >> 1; if (ends[mid] <= fp) lo = mid + 1; else hi = mid; }
        int id = lo < TE - 1 ? lo : TE - 1;
        idx[bb * TD + tp] = id;
        mask[bb * TD + tp] = fp < total ? 1.f : 0.f;
    }
}
__global__ void gather_k(const float* __restrict__ enc, const int* __restrict__ idx,
                         const float* __restrict__ mask, float* __restrict__ out) {
    int i = blockIdx.x * blockDim.x + threadIdx.x;
    if (i >= MD * DM) return;
    int c = i % DM;
    int r = i / DM;
    int bb = r / TD;
    out[i] = enc[(size_t)(bb * TE + idx[r]) * DM + c] * mask[r];
}

// ---------------- rmsnorm ----------------
__global__ void rmsnorm_k(const float* __restrict__ x, const float* __restrict__ g,
                          float* __restrict__ out) {
    int r = blockIdx.x;
    const float* xr = x + (size_t)r * DM;
    float s = 0.f;
    for (int c = threadIdx.x; c < DM; c += blockDim.x) { float v = xr[c]; s = fmaf(v, v, s); }
    __shared__ float red[4];
    #pragma unroll
    for (int o = 16; o; o >>= 1) s += __shfl_xor_sync(0xffffffffu, s, o);
    int w = threadIdx.x >> 5;
    if ((threadIdx.x & 31) == 0) red[w] = s;
    __syncthreads();
    if (threadIdx.x == 0) red[0] = red[0] + red[1] + red[2] + red[3];
    __syncthreads();
    float scale = rsqrtf(red[0] / (float)DM + 1e-6f);
    for (int c = threadIdx.x; c < DM; c += blockDim.x)
        out[(size_t)r * DM + c] = xr[c] * scale * g[c];
}

// ---------------- mel projection (N=80, bounds-checked) ----------------
__global__ __launch_bounds__(256) void melgemm_k(
    const float* __restrict__ A, const float* __restrict__ W, float* __restrict__ C,
    int M, int N, int K, int lda, int ldb, int ldc, const float* __restrict__ rmask)
{
    __shared__ float As[16][64];
    __shared__ float Bs[16][64];
    const int bm = blockIdx.y * 64, bn = blockIdx.x * 64;
    const int tid = threadIdx.x;
    const int tx = tid & 15, ty = tid >> 4;
    const int am = tid >> 2, ak = (tid & 3) << 2;
    const int bk = tid >> 4, bn4 = (tid & 15) << 2;
    float acc[4][4] = {};
    for (int k0 = 0; k0 < K; k0 += 16) {
        float4 av = make_float4(0.f, 0.f, 0.f, 0.f);
        if (bm + am < M)
            av = *reinterpret_cast<const float4*>(A + (size_t)(bm + am) * lda + k0 + ak);
        As[ak + 0][am] = av.x; As[ak + 1][am] = av.y;
        As[ak + 2][am] = av.z; As[ak + 3][am] = av.w;
        float4 bv;
        const float* wr = W + (size_t)(k0 + bk) * ldb;
        bv.x = (bn + bn4 + 0 < N) ? wr[bn + bn4 + 0] : 0.f;
        bv.y = (bn + bn4 + 1 < N) ? wr[bn + bn4 + 1] : 0.f;
        bv.z = (bn + bn4 + 2 < N) ? wr[bn + bn4 + 2] : 0.f;
        bv.w = (bn + bn4 + 3 < N) ? wr[bn + bn4 + 3] : 0.f;
        Bs[bk][bn4 + 0] = bv.x; Bs[bk][bn4 + 1] = bv.y;
        Bs[bk][bn4 + 2] = bv.z; Bs[bk][bn4 + 3] = bv.w;
        __syncthreads();
        #pragma unroll
        for (int kk = 0; kk < 16; kk++) {
            float af[4], bf[4];
            #pragma unroll
            for (int i = 0; i < 4; i++) af[i] = As[kk][(ty << 2) + i];
            #pragma unroll
            for (int j = 0; j < 4; j++) bf[j] = Bs[kk][(tx << 2) + j];
            #pragma unroll
            for (int i = 0; i < 4; i++)
                #pragma unroll
                for (int j = 0; j < 4; j++)
                    acc[i][j] = fmaf(af[i], bf[j], acc[i][j]);
        }
        __syncthreads();
    }
    #pragma unroll
    for (int i = 0; i < 4; i++) {
        int m = bm + (ty << 2) + i;
        if (m >= M) continue;
        #pragma unroll
        for (int j = 0; j < 4; j++) {
            int n = bn + (tx << 2) + j;
            if (n >= N) continue;
            C[(size_t)m * ldc + n] = acc[i][j] * rmask[m];
        }
    }
}

__global__ void tail_k(float* __restrict__ out, const float* __restrict__ mask, int n) {
    int i = blockIdx.x * blockDim.x + threadIdx.x;
    if (i >= n) return;
    out[i] = (i < NB * TD) ? mask[i] : 0.f;
}

// ---------------- host driver ----------------
extern "C" void kernel_launch(void* const* d_in, const int* in_sizes, int n_in,
                              void* d_out, int out_size) {
    (void)n_in;
    int map[32];
    if (in_sizes[2] == 3 * DM * 2 * DI) {
        for (int i = 0; i < 32; i++) map[i] = i;
    } else {
        const int m[32] = {0, 1,
                           14, 15, 16, 17, 18, 19, 20, 21, 22,
                           2, 3, 4, 5, 6, 7, 8, 9, 10, 11,
                           23, 24, 25, 26, 27, 28, 29, 30, 31,
                           12, 13};
        for (int i = 0; i < 32; i++) map[i] = m[i];
    }
    const int*   text      = (const int*)  d_in[map[0]];
    const float* emb       = (const float*)d_in[map[1]];
    const float* enc_in_w  = (const float*)d_in[map[2]];
    const float* enc_cw    = (const float*)d_in[map[3]];
    const float* enc_cb    = (const float*)d_in[map[4]];
    const float* enc_xpw   = (const float*)d_in[map[5]];
    const float* enc_dtw   = (const float*)d_in[map[6]];
    const float* enc_dtb   = (const float*)d_in[map[7]];
    const float* enc_alog  = (const float*)d_in[map[8]];
    const float* enc_dp    = (const float*)d_in[map[9]];
    const float* enc_ow    = (const float*)d_in[map[10]];
    const float* dp_c1w    = (const float*)d_in[map[11]];
    const float* dp_c1b    = (const float*)d_in[map[12]];
    const float* dp_g1     = (const float*)d_in[map[13]];
    const float* dp_b1     = (const float*)d_in[map[14]];
    const float* dp_c2w    = (const float*)d_in[map[15]];
    const float* dp_c2b    = (const float*)d_in[map[16]];
    const float* dp_g2     = (const float*)d_in[map[17]];
    const float* dp_b2     = (const float*)d_in[map[18]];
    const float* dp_c3w    = (const float*)d_in[map[19]];
    const float* dp_c3b    = (const float*)d_in[map[20]];
    const float* dec_in_w  = (const float*)d_in[map[21]];
    const float* dec_cw    = (const float*)d_in[map[22]];
    const float* dec_cb    = (const float*)d_in[map[23]];
    const float* dec_xpw   = (const float*)d_in[map[24]];
    const float* dec_dtw   = (const float*)d_in[map[25]];
    const float* dec_dtb   = (const float*)d_in[map[26]];
    const float* dec_alog  = (const float*)d_in[map[27]];
    const float* dec_dpv   = (const float*)d_in[map[28]];
    const float* dec_ow    = (const float*)d_in[map[29]];
    const float* norm_g    = (const float*)d_in[map[30]];
    const float* out_w     = (const float*)d_in[map[31]];

    float *x0, *x1, *xz, *u, *xdbl, *part, *delta, *gate, *im, *wt, *h1, *h2, *dur, *mask;
    int* idx;
    __nv_bfloat16 *aext, *wext;
    cudaGetSymbolAddress((void**)&x0,    g_x0);
    cudaGetSymbolAddress((void**)&x1,    g_x1);
    cudaGetSymbolAddress((void**)&xz,    g_xz);
    cudaGetSymbolAddress((void**)&u,     g_u);
    cudaGetSymbolAddress((void**)&xdbl,  g_xdbl);
    cudaGetSymbolAddress((void**)&part,  g_part);
    cudaGetSymbolAddress((void**)&delta, g_delta);
    cudaGetSymbolAddress((void**)&gate,  g_gate);
    cudaGetSymbolAddress((void**)&im,    g_im2col);
    cudaGetSymbolAddress((void**)&wt,    g_wt);
    cudaGetSymbolAddress((void**)&h1,    g_h1);
    cudaGetSymbolAddress((void**)&h2,    g_h2);
    cudaGetSymbolAddress((void**)&dur,   g_dur);
    cudaGetSymbolAddress((void**)&idx,   g_idx);
    cudaGetSymbolAddress((void**)&mask,  g_mask);
    cudaGetSymbolAddress((void**)&aext,  g_aext);
    cudaGetSymbolAddress((void**)&wext,  g_wext);

    // TC GEMM helper: C[M,N] = A[M,K] @ W[K,N]  (+epilogue)
    auto tcgemm = [&](int epi, const float* A, const float* W, float* C, int M, int N, int K,
                      const float* bias, const float* gamma, const float* beta) {
        split_w_k<<<dim3(N / 32, K / 32), dim3(32, 32)>>>(W, wext, K, N);
        split_a_k<<<(M * K + 255) / 256, 256>>>(A, aext, M * K, K);
        dim3 grid(N / 128, M / 128);
        if (epi == 2)
            hmma_k<2><<<grid, 256>>>(aext, wext, C, 3 * K, N, bias, gamma, beta);
        else
            hmma_k<0><<<grid, 256>>>(aext, wext, C, 3 * K, N, nullptr, nullptr, nullptr);
    };

    auto mamba = [&](const float* xin, float* xout, int L, int l,
                     const float* inw, const float* cw, const float* cb,
                     const float* xpw, const float* dtw, const float* dtb,
                     const float* alog, const float* dp, const float* ow) {
        int M = NB * L;
        // in_proj: [M,512] @ [512,2048]   (tensor core)
        tcgemm(0, xin, inw + (size_t)l * DM * 2 * DI, xz, M, 2 * DI, DM, nullptr, nullptr, nullptr);
        int tot = M * DI;
        dwconv_silu_k<<<(tot + 255) / 256, 256>>>(xz, cw + (size_t)l * DI * 4,
                                                  cb + (size_t)l * DI, u, L);
        // xproj split-K (fp32): [M,1024] @ [1024,64]
        xp_k<<<dim3(M / 64, KS), 256>>>(u, xpw + (size_t)l * DI * 64, part, M);
        xp_reduce_k<<<(M * 16 + 255) / 256, 256>>>(part, xdbl, M);
        // dt (fp32, K=32): softplus([M,32] @ [32,1024] + b)
        gemm64_k<1><<<dim3(DI / 64, M / 64), 256>>>(
            xdbl, dtw + (size_t)l * DTR * DI, delta, DTR, 64, DI, DI,
            dtb + (size_t)l * DI, nullptr, nullptr);
        scan_k<<<(NB * DI * 4 + 127) / 128, 128>>>(xdbl, delta, u, xz,
                                                   alog + (size_t)l * DI * DS,
                                                   dp + (size_t)l * DI, gate, L);
        // out_proj: [M,1024] @ [1024,512]  (tensor core)
        tcgemm(0, gate, ow + (size_t)l * DI * DM, xout, M, DM, DI, nullptr, nullptr, nullptr);
    };

    embed_k<<<(ME * DM + 255) / 256, 256>>>(text, emb, x0);

    mamba(x0, x1, TE, 0, enc_in_w, enc_cw, enc_cb, enc_xpw, enc_dtw, enc_dtb, enc_alog, enc_dp, enc_ow);
    mamba(x1, x0, TE, 1, enc_in_w, enc_cw, enc_cb, enc_xpw, enc_dtw, enc_dtb, enc_alog, enc_dp, enc_ow);
    mamba(x0, x1, TE, 2, enc_in_w, enc_cw, enc_cb, enc_xpw, enc_dtw, enc_dtb, enc_alog, enc_dp, enc_ow);

    // duration predictor on x1 (tensor core convs)
    wt_k<<<(DM * DM * 3 + 255) / 256, 256>>>(dp_c1w, wt);
    im2col_k<<<(ME * DM * 3 + 255) / 256, 256>>>(x1, im);
    tcgemm(2, im, wt, h1, ME, DM, 3 * DM, dp_c1b, dp_g1, dp_b1);
    wt_k<<<(DM * DM * 3 + 255) / 256, 256>>>(dp_c2w, wt);
    im2col_k<<<(ME * DM * 3 + 255) / 256, 256>>>(h1, im);
    tcgemm(2, im, wt, h2, ME, DM, 3 * DM, dp_c2b, dp_g2, dp_b2);
    dur_k<<<(ME * 32 + 255) / 256, 256>>>(h2, dp_c3w, dp_c3b, dur);

    expand_k<<<NB, TE>>>(dur, idx, mask);
    gather_k<<<(MD * DM + 255) / 256, 256>>>(x1, idx, mask, x0);

    mamba(x0, x1, TD, 0, dec_in_w, dec_cw, dec_cb, dec_xpw, dec_dtw, dec_dtb, dec_alog, dec_dpv, dec_ow);
    mamba(x1, x0, TD, 1, dec_in_w, dec_cw, dec_cb, dec_xpw, dec_dtw, dec_dtb, dec_alog, dec_dpv, dec_ow);
    mamba(x0, x1, TD, 2, dec_in_w, dec_cw, dec_cb, dec_xpw, dec_dtw, dec_dtb, dec_alog, dec_dpv, dec_ow);

    rmsnorm_k<<<MD, 128>>>(x1, norm_g, x0);
    melgemm_k<<<dim3((NM + 63) / 64, MD / 64), 256>>>(
        x0, out_w, (float*)d_out, MD, NM, DM, DM, NM, NM, mask);

    int melN = MD * NM;
    if (out_size > melN) {
        int n = out_size - melN;
        tail_k<<<(n + 255) / 256, 256>>>((float*)d_out + melN, mask, n);
    }
}

// round 7
// speedup vs baseline: 1.0503x; 1.0503x over previous
#include <cuda_runtime.h>
#include <cuda_bf16.h>
#include <math.h>
#include <stdint.h>

namespace {
constexpr int NB = 4, TE = 256, TD = 512, DM = 512, DI = 1024, DS = 16, DTR = 32, NM = 80;
constexpr int ME = NB * TE;   // 1024 encoder rows
constexpr int MD = NB * TD;   // 2048 decoder rows
constexpr int KS = 8;         // xproj split-K factor
constexpr int PITCH = 40;     // smem halves per row (80B) -> conflict-free ldmatrix
constexpr int ST = 4;         // cp.async stages
constexpr int STAGE_B = 128 * PITCH * 2;       // 10240 bytes per matrix per stage
constexpr int HS = 2 * ST * STAGE_B;           // 81920 dynamic smem
}

// ---------------- scratch ----------------
__device__ float g_x0[MD * DM];
__device__ float g_x1[MD * DM];
__device__ float g_xz[MD * 2 * DI];
__device__ float g_u[MD * DI];
__device__ float g_xdbl[MD * 64];
__device__ float g_part[KS * MD * 64];
__device__ float g_delta[MD * DI];
__device__ float g_im2col_unused[1];
__device__ float g_wt[DM * 3 * DM];
__device__ float g_h1[ME * DM];
__device__ float g_h2[ME * DM];
__device__ float g_dur[ME];
__device__ int   g_idx[NB * TD];
__device__ float g_mask[NB * TD];
__device__ uint4 g_wext[393216];   // weight ext: up to 2048*1536 bf16
__device__ uint4 g_xe[393216];     // x ext:  MD*1536 bf16 = 3145728
__device__ uint4 g_ge[786432];     // gate ext: MD*3072 bf16 = 6291456
__device__ uint4 g_ime[589824];    // im2col ext: ME*4608 bf16 = 4718592

__device__ __forceinline__ float softplus_f(float x) {
    return x > 0.f ? x + log1pf(expf(-x)) : log1pf(expf(x));
}
__device__ __forceinline__ float silu_f(float x) {
    return x / (1.f + expf(-x));
}
__device__ __forceinline__ uint32_t smem_u32(const void* p) {
    uint32_t a;
    asm("{ .reg .u64 t; cvta.to.shared.u64 t, %1; cvt.u32.u64 %0, t; }" : "=r"(a) : "l"(p));
    return a;
}
#define CP_ASYNC16(dst, src) asm volatile("cp.async.cg.shared.global [%0], [%1], 16;" :: "r"(dst), "l"(src))
#define CP_COMMIT()          asm volatile("cp.async.commit_group;")
#define CP_WAIT(n)           asm volatile("cp.async.wait_group %0;" :: "n"(n))

// write the 3-slab A-ext entry for value a at (row, k) with inner length K:
// [k]=hi, [K+k]=hi, [2K+k]=lo
__device__ __forceinline__ void write_aext(__nv_bfloat16* e, size_t row, int K, int k, float a) {
    __nv_bfloat16 hi = __float2bfloat16_rn(a);
    __nv_bfloat16 lo = __float2bfloat16_rn(a - __bfloat162float(hi));
    size_t base = row * (size_t)(3 * K);
    e[base + k] = hi;
    e[base + K + k] = hi;
    e[base + 2 * K + k] = lo;
}

// ================= weight split (B ext: [N][3K], row n = [hi|lo|hi]) =================
__global__ void split_w_k(const float* __restrict__ W, __nv_bfloat16* __restrict__ out,
                          int K, int N) {
    __shared__ float tile[32][33];
    int n0 = blockIdx.x * 32, k0 = blockIdx.y * 32;
    int tx = threadIdx.x, ty = threadIdx.y;
    tile[ty][tx] = W[(size_t)(k0 + ty) * N + n0 + tx];
    __syncthreads();
    int n = n0 + ty, k = k0 + tx;
    float a = tile[tx][ty];
    __nv_bfloat16 hi = __float2bfloat16_rn(a);
    __nv_bfloat16 lo = __float2bfloat16_rn(a - __bfloat162float(hi));
    size_t base = (size_t)n * 3 * K;
    out[base + k] = hi;
    out[base + K + k] = lo;
    out[base + 2 * K + k] = hi;
}

// ================= HMMA bf16 GEMM with cp.async pipeline =================
// C[M,N] = Aext[M,K3] @ Bext[N,K3]^T.  128x128 block, BK=32, 8 warps (2x4).
// EPI: 0=none, 2=relu(+bias)*bn_scale+bn_shift.  WEXT: also write Cext [M][3N] = [hi|hi|lo].
template<int EPI, int WEXT>
__global__ __launch_bounds__(256) void hmma_k(
    const __nv_bfloat16* __restrict__ Ae, const __nv_bfloat16* __restrict__ Be,
    float* __restrict__ C, __nv_bfloat16* __restrict__ Cext, int K3, int N,
    const float* __restrict__ bias, const float* __restrict__ gamma,
    const float* __restrict__ beta)
{
    extern __shared__ char dsm[];
    const uint32_t saA = smem_u32(dsm);
    const uint32_t saB = saA + ST * STAGE_B;

    const int tid = threadIdx.x, lane = tid & 31, w = tid >> 5;
    const int wm = w & 1, wn = w >> 1;              // 2 x 4 warp grid
    const int bm = blockIdx.y * 128, bn = blockIdx.x * 128;
    const size_t arow = (size_t)K3 * 2;             // bytes per ext row

    const char* Ag = (const char*)Ae + (size_t)bm * arow;
    const char* Bg = (const char*)Be + (size_t)bn * arow;
    const int ldr = tid >> 2, lds = tid & 3;        // 128 rows x 4 x 16B segs

    auto issue = [&](int kc, int s) {
        const size_t go = (size_t)ldr * arow + (size_t)kc * 64 + lds * 16;
        const size_t g2 = go + (size_t)64 * arow;
        const uint32_t da = saA + s * STAGE_B + ldr * 80 + lds * 16;
        const uint32_t db = saB + s * STAGE_B + ldr * 80 + lds * 16;
        CP_ASYNC16(da, Ag + go);
        CP_ASYNC16(da + 64 * 80, Ag + g2);
        CP_ASYNC16(db, Bg + go);
        CP_ASYNC16(db + 64 * 80, Bg + g2);
    };

    float acc[4][4][4] = {};

    const int a_row = wm * 64 + (lane & 15);        // + mt*16
    const int a_kof = (lane >> 4) * 8;              // + ks*16
    const int bl = lane & 15;
    const int b_row = wn * 32 + (bl & 7);           // + nt*8
    const int b_kof = (bl >> 3) * 8;                // + ks*16

    auto compute = [&](int s) {
        const uint32_t abase = saA + s * STAGE_B;
        const uint32_t bbase = saB + s * STAGE_B;
        #pragma unroll
        for (int ks = 0; ks < 2; ks++) {
            uint32_t af[4][4];
            #pragma unroll
            for (int mt = 0; mt < 4; mt++) {
                uint32_t addr = abase + (a_row + mt * 16) * 80 + (a_kof + ks * 16) * 2;
                asm volatile("ldmatrix.sync.aligned.m8n8.x4.shared.b16 {%0,%1,%2,%3}, [%4];"
                    : "=r"(af[mt][0]), "=r"(af[mt][1]), "=r"(af[mt][2]), "=r"(af[mt][3])
                    : "r"(addr));
            }
            uint32_t bf[4][2];
            #pragma unroll
            for (int nt = 0; nt < 4; nt++) {
                uint32_t addr = bbase + (b_row + nt * 8) * 80 + (b_kof + ks * 16) * 2;
                asm volatile("ldmatrix.sync.aligned.m8n8.x2.shared.b16 {%0,%1}, [%2];"
                    : "=r"(bf[nt][0]), "=r"(bf[nt][1])
                    : "r"(addr));
            }
            #pragma unroll
            for (int mt = 0; mt < 4; mt++)
                #pragma unroll
                for (int nt = 0; nt < 4; nt++) {
                    asm volatile(
                        "mma.sync.aligned.m16n8k16.row.col.f32.bf16.bf16.f32 "
                        "{%0,%1,%2,%3}, {%4,%5,%6,%7}, {%8,%9}, {%0,%1,%2,%3};"
                        : "+f"(acc[mt][nt][0]), "+f"(acc[mt][nt][1]),
                          "+f"(acc[mt][nt][2]), "+f"(acc[mt][nt][3])
                        : "r"(af[mt][0]), "r"(af[mt][1]), "r"(af[mt][2]), "r"(af[mt][3]),
                          "r"(bf[nt][0]), "r"(bf[nt][1]));
                }
        }
    };

    const int NC = K3 / 32;
    #pragma unroll
    for (int s = 0; s < ST - 1; s++) { if (s < NC) issue(s, s); CP_COMMIT(); }
    for (int kc = 0; kc < NC; kc++) {
        CP_WAIT(ST - 2);
        __syncthreads();
        compute(kc & (ST - 1));
        __syncthreads();
        int nx = kc + ST - 1;
        if (nx < NC) issue(nx, nx & (ST - 1));
        CP_COMMIT();
    }

    // epilogue: C fragments -> global (float2 stores) + optional A-ext for next GEMM
    const int tq = lane >> 2, tr = lane & 3;
    #pragma unroll
    for (int mt = 0; mt < 4; mt++) {
        #pragma unroll
        for (int nt = 0; nt < 4; nt++) {
            int row0 = bm + wm * 64 + mt * 16 + tq;
            int col = bn + wn * 32 + nt * 8 + tr * 2;
            float v[4] = {acc[mt][nt][0], acc[mt][nt][1], acc[mt][nt][2], acc[mt][nt][3]};
            if (EPI == 2) {
                #pragma unroll
                for (int e = 0; e < 4; e++) {
                    int n = col + (e & 1);
                    v[e] = fmaxf(v[e] + bias[n], 0.f) * (gamma[n] * rsqrtf(1.f + 1e-5f)) + beta[n];
                }
            }
            *reinterpret_cast<float2*>(C + (size_t)row0 * N + col) = make_float2(v[0], v[1]);
            *reinterpret_cast<float2*>(C + (size_t)(row0 + 8) * N + col) = make_float2(v[2], v[3]);
            if (WEXT) {
                #pragma unroll
                for (int h = 0; h < 2; h++) {
                    float a0 = v[h * 2], a1 = v[h * 2 + 1];
                    __nv_bfloat16 h0 = __float2bfloat16_rn(a0), h1 = __float2bfloat16_rn(a1);
                    __nv_bfloat16 l0 = __float2bfloat16_rn(a0 - __bfloat162float(h0));
                    __nv_bfloat16 l1 = __float2bfloat16_rn(a1 - __bfloat162float(h1));
                    size_t base = (size_t)(row0 + h * 8) * (3 * N);
                    __nv_bfloat162 hv = __halves2bfloat162(h0, h1);
                    __nv_bfloat162 lv = __halves2bfloat162(l0, l1);
                    *reinterpret_cast<__nv_bfloat162*>(Cext + base + col) = hv;
                    *reinterpret_cast<__nv_bfloat162*>(Cext + base + N + col) = hv;
                    *reinterpret_cast<__nv_bfloat162*>(Cext + base + 2 * N + col) = lv;
                }
            }
        }
    }
}

// ---------------- embedding: fp32 + x-ext ----------------
__global__ void embed_k(const int* __restrict__ text, const float* __restrict__ emb,
                        float* __restrict__ out, __nv_bfloat16* __restrict__ oute) {
    int i = blockIdx.x * blockDim.x + threadIdx.x;
    if (i >= ME * DM) return;
    int c = i % DM;
    int r = i / DM;
    float v = emb[text[r] * DM + c];
    out[i] = v;
    write_aext(oute, r, DM, c, v);
}

// ============ gemm64 (fp32): dt projection (K=32) ============
template<int EPI>
__global__ __launch_bounds__(256) void gemm64_k(
    const float* __restrict__ A, const float* __restrict__ W, float* __restrict__ C,
    int K, int lda, int ldb, int ldc,
    const float* __restrict__ bias, const float* __restrict__ gamma,
    const float* __restrict__ beta)
{
    __shared__ float As[2][16][64];
    __shared__ float Bs[2][16][64];
    const int tid = threadIdx.x;
    const int tx = tid & 15, ty = tid >> 4;
    const int bm = blockIdx.y * 64, bn = blockIdx.x * 64;
    const int ar = tid >> 2, ac = (tid & 3) << 2;
    const int br = tid >> 4, bc = (tid & 15) << 2;
    const float* Ag = A + (size_t)(bm + ar) * lda + ac;
    const float* Wg = W + bn + bc;

    float4 ap, bp;
    auto ld = [&](int k0) {
        ap = *reinterpret_cast<const float4*>(Ag + k0);
        bp = *reinterpret_cast<const float4*>(Wg + (size_t)(k0 + br) * ldb);
    };
    auto st = [&](int buf) {
        As[buf][ac + 0][ar] = ap.x; As[buf][ac + 1][ar] = ap.y;
        As[buf][ac + 2][ar] = ap.z; As[buf][ac + 3][ar] = ap.w;
        *reinterpret_cast<float4*>(&Bs[buf][br][bc]) = bp;
    };

    float acc[4][4] = {};
    const int KB = K / 16;
    ld(0); st(0); __syncthreads();
    for (int kb = 0; kb < KB; kb++) {
        const int cur = kb & 1;
        if (kb + 1 < KB) ld((kb + 1) * 16);
        #pragma unroll
        for (int kk = 0; kk < 16; kk++) {
            float a[4], b[4];
            *reinterpret_cast<float4*>(a) = *reinterpret_cast<const float4*>(&As[cur][kk][ty * 4]);
            *reinterpret_cast<float4*>(b) = *reinterpret_cast<const float4*>(&Bs[cur][kk][tx * 4]);
            #pragma unroll
            for (int i = 0; i < 4; i++)
                #pragma unroll
                for (int j = 0; j < 4; j++)
                    acc[i][j] = fmaf(a[i], b[j], acc[i][j]);
        }
        if (kb + 1 < KB) st(1 - cur);
        __syncthreads();
    }
    #pragma unroll
    for (int i = 0; i < 4; i++) {
        const int m = bm + ty * 4 + i;
        const int n0 = bn + tx * 4;
        float4 v;
        float* pv = &v.x;
        #pragma unroll
        for (int q = 0; q < 4; q++) {
            float x = acc[i][q];
            if (EPI == 1) x = softplus_f(x + bias[n0 + q]);
            pv[q] = x;
        }
        *reinterpret_cast<float4*>(C + (size_t)m * ldc + n0) = v;
    }
}

// ============ xproj split-K (fp32) ============
__global__ __launch_bounds__(256) void xp_k(
    const float* __restrict__ A, const float* __restrict__ W, float* __restrict__ P, int M)
{
    __shared__ float As[2][16][64];
    __shared__ float Bs[2][16][64];
    const int tid = threadIdx.x;
    const int tx = tid & 15, ty = tid >> 4;
    const int bm = blockIdx.x * 64;
    const int kz = blockIdx.y;
    const int kbase = kz * (DI / KS);
    const int ar = tid >> 2, ac = (tid & 3) << 2;
    const int br = tid >> 4, bc = (tid & 15) << 2;
    const float* Ag = A + (size_t)(bm + ar) * DI + kbase + ac;
    const float* Wg = W + (size_t)kbase * 64 + bc;

    float4 ap, bp;
    auto ld = [&](int k0) {
        ap = *reinterpret_cast<const float4*>(Ag + k0);
        bp = *reinterpret_cast<const float4*>(Wg + (size_t)(k0 + br) * 64);
    };
    auto st = [&](int buf) {
        As[buf][ac + 0][ar] = ap.x; As[buf][ac + 1][ar] = ap.y;
        As[buf][ac + 2][ar] = ap.z; As[buf][ac + 3][ar] = ap.w;
        *reinterpret_cast<float4*>(&Bs[buf][br][bc]) = bp;
    };

    float acc[4][4] = {};
    const int KB = (DI / KS) / 16;
    ld(0); st(0); __syncthreads();
    for (int kb = 0; kb < KB; kb++) {
        const int cur = kb & 1;
        if (kb + 1 < KB) ld((kb + 1) * 16);
        #pragma unroll
        for (int kk = 0; kk < 16; kk++) {
            float a[4], b[4];
            *reinterpret_cast<float4*>(a) = *reinterpret_cast<const float4*>(&As[cur][kk][ty * 4]);
            *reinterpret_cast<float4*>(b) = *reinterpret_cast<const float4*>(&Bs[cur][kk][tx * 4]);
            #pragma unroll
            for (int i = 0; i < 4; i++)
                #pragma unroll
                for (int j = 0; j < 4; j++)
                    acc[i][j] = fmaf(a[i], b[j], acc[i][j]);
        }
        if (kb + 1 < KB) st(1 - cur);
        __syncthreads();
    }
    float* Pg = P + ((size_t)kz * M + bm) * 64;
    #pragma unroll
    for (int i = 0; i < 4; i++) {
        float4 v = make_float4(acc[i][0], acc[i][1], acc[i][2], acc[i][3]);
        *reinterpret_cast<float4*>(Pg + (size_t)(ty * 4 + i) * 64 + tx * 4) = v;
    }
}

__global__ void xp_reduce_k(const float* __restrict__ P, float* __restrict__ out, int M) {
    int i = blockIdx.x * blockDim.x + threadIdx.x;
    if (i >= M * 16) return;
    float4 s = make_float4(0.f, 0.f, 0.f, 0.f);
    #pragma unroll
    for (int z = 0; z < KS; z++) {
        float4 v = *reinterpret_cast<const float4*>(P + ((size_t)z * M * 16 + i) * 4);
        s.x += v.x; s.y += v.y; s.z += v.z; s.w += v.w;
    }
    *reinterpret_cast<float4*>(out + (size_t)i * 4) = s;
}

// ---------------- depthwise causal conv (K=4) + SiLU ----------------
__global__ void dwconv_silu_k(const float* __restrict__ xz, const float* __restrict__ w,
                              const float* __restrict__ bcv, float* __restrict__ u, int L) {
    int i = blockIdx.x * blockDim.x + threadIdx.x;
    int total = NB * L * DI;
    if (i >= total) return;
    int d = i % DI;
    int bt = i / DI;
    int t = bt % L;
    int bb = bt / L;
    float acc = bcv[d];
    const float* wr = w + d * 4;
    #pragma unroll
    for (int k = 0; k < 4; k++) {
        int ts = t - 3 + k;
        if (ts >= 0)
            acc = fmaf(wr[k], xz[((size_t)(bb * L + ts)) * 2048 + d], acc);
    }
    u[i] = silu_f(acc);
}

// ---------------- selective scan: 8 threads/(b,d), 2 states each, writes gate-ext ----------------
__global__ void scan_k(const float* __restrict__ xdbl, const float* __restrict__ delta,
                       const float* __restrict__ u, const float* __restrict__ xz,
                       const float* __restrict__ Alog, const float* __restrict__ Dp,
                       __nv_bfloat16* __restrict__ ge, int L) {
    int gt = blockIdx.x * blockDim.x + threadIdx.x;
    if (gt >= NB * DI * 8) return;
    int lane = gt & 7;
    int gid = gt >> 3;
    int d = gid % DI;
    int bb = gid / DI;
    float a0 = -expf(Alog[d * DS + lane * 2 + 0]);
    float a1 = -expf(Alog[d * DS + lane * 2 + 1]);
    float Dd = Dp[d];
    float h0 = 0.f, h1 = 0.f;

    float dl, ut, rs;
    float2 Bv, Cv;
    auto loadt = [&](int t, float& dl_, float& ut_, float2& B_, float2& C_, float& rs_) {
        size_t row = (size_t)bb * L + t;
        dl_ = delta[row * DI + d];
        ut_ = u[row * DI + d];
        const float* xd = xdbl + row * 64;
        B_ = *reinterpret_cast<const float2*>(xd + 32 + lane * 2);
        C_ = *reinterpret_cast<const float2*>(xd + 48 + lane * 2);
        rs_ = xz[row * 2048 + 1024 + d];
    };
    loadt(0, dl, ut, Bv, Cv, rs);
    for (int t = 0; t < L; t++) {
        float dl2, ut2, rs2;
        float2 Bv2, Cv2;
        if (t + 1 < L) loadt(t + 1, dl2, ut2, Bv2, Cv2, rs2);
        float du = dl * ut;
        h0 = fmaf(__expf(dl * a0), h0, du * Bv.x);
        h1 = fmaf(__expf(dl * a1), h1, du * Bv.y);
        float y = h0 * Cv.x + h1 * Cv.y;
        y += __shfl_xor_sync(0xffffffffu, y, 1);
        y += __shfl_xor_sync(0xffffffffu, y, 2);
        y += __shfl_xor_sync(0xffffffffu, y, 4);
        if (lane == 0) {
            size_t row = (size_t)bb * L + t;
            float g = (y + ut * Dd) * silu_f(rs);
            write_aext(ge, row, DI, d, g);
        }
        dl = dl2; ut = ut2; Bv = Bv2; Cv = Cv2; rs = rs2;
    }
}

// ---------------- duration predictor helpers ----------------
__global__ void wt_k(const float* __restrict__ w, float* __restrict__ wt) {
    int i = blockIdx.x * blockDim.x + threadIdx.x;
    if (i >= DM * DM * 3) return;
    int k = i % 3;
    int c = (i / 3) % DM;
    int d = i / (3 * DM);
    wt[(size_t)(k * DM + c) * DM + d] = w[i];
}
// im2col straight to A-ext: row r, inner K = 1536 (k*512+c)
__global__ void im2col_k(const float* __restrict__ src, __nv_bfloat16* __restrict__ dste) {
    int i = blockIdx.x * blockDim.x + threadIdx.x;
    if (i >= ME * DM * 3) return;
    int c = i % DM;
    int k = (i / DM) % 3;
    int r = i / (DM * 3);
    int t = r % TE;
    int ts = t - 1 + k;
    float v = 0.f;
    if (ts >= 0 && ts < TE) v = src[(size_t)(r - t + ts) * DM + c];
    write_aext(dste, r, 3 * DM, k * DM + c, v);
}
__global__ void dur_k(const float* __restrict__ h2, const float* __restrict__ w3,
                      const float* __restrict__ b3, float* __restrict__ dur) {
    int warp = (blockIdx.x * blockDim.x + threadIdx.x) >> 5;
    int lane = threadIdx.x & 31;
    if (warp >= ME) return;
    const float* hr = h2 + (size_t)warp * DM;
    float s = 0.f;
    for (int c = lane; c < DM; c += 32) s = fmaf(hr[c], w3[c], s);
    #pragma unroll
    for (int o = 16; o; o >>= 1) s += __shfl_xor_sync(0xffffffffu, s, o);
    if (lane == 0) dur[warp] = softplus_f(s + b3[0]);
}

// ---------------- length regulator ----------------
__global__ void expand_k(const float* __restrict__ dur, int* __restrict__ idx,
                         float* __restrict__ mask) {
    __shared__ float ends[TE];
    int bb = blockIdx.x;
    int t = threadIdx.x;
    ends[t] = rintf(fmaxf(dur[bb * TE + t], 0.f));
    __syncthreads();
    if (t == 0) {
        float s = 0.f;
        for (int i = 0; i < TE; i++) { s += ends[i]; ends[i] = s; }
    }
    __syncthreads();
    float total = ends[TE - 1];
    for (int tp = t; tp < TD; tp += TE) {
        float fp = (float)tp;
        int lo = 0, hi = TE;
        while (lo < hi) { int mid = (lo + hi) >> 1; if (ends[mid] <= fp) lo = mid + 1; else hi = mid; }
        int id = lo < TE - 1 ? lo : TE - 1;
        idx[bb * TD + tp] = id;
        mask[bb * TD + tp] = fp < total ? 1.f : 0.f;
    }
}
// gather -> decoder in_proj A-ext only
__global__ void gather_k(const float* __restrict__ enc, const int* __restrict__ idx,
                         const float* __restrict__ mask, __nv_bfloat16* __restrict__ oute) {
    int i = blockIdx.x * blockDim.x + threadIdx.x;
    if (i >= MD * DM) return;
    int c = i % DM;
    int r = i / DM;
    int bb = r / TD;
    float v = enc[(size_t)(bb * TE + idx[r]) * DM + c] * mask[r];
    write_aext(oute, r, DM, c, v);
}

// ---------------- rmsnorm ----------------
__global__ void rmsnorm_k(const float* __restrict__ x, const float* __restrict__ g,
                          float* __restrict__ out) {
    int r = blockIdx.x;
    const float* xr = x + (size_t)r * DM;
    float s = 0.f;
    for (int c = threadIdx.x; c < DM; c += blockDim.x) { float v = xr[c]; s = fmaf(v, v, s); }
    __shared__ float red[4];
    #pragma unroll
    for (int o = 16; o; o >>= 1) s += __shfl_xor_sync(0xffffffffu, s, o);
    int w = threadIdx.x >> 5;
    if ((threadIdx.x & 31) == 0) red[w] = s;
    __syncthreads();
    if (threadIdx.x == 0) red[0] = red[0] + red[1] + red[2] + red[3];
    __syncthreads();
    float scale = rsqrtf(red[0] / (float)DM + 1e-6f);
    for (int c = threadIdx.x; c < DM; c += blockDim.x)
        out[(size_t)r * DM + c] = xr[c] * scale * g[c];
}

// ---------------- mel projection (N=80, bounds-checked) ----------------
__global__ __launch_bounds__(256) void melgemm_k(
    const float* __restrict__ A, const float* __restrict__ W, float* __restrict__ C,
    int M, int N, int K, int lda, int ldb, int ldc, const float* __restrict__ rmask)
{
    __shared__ float As[16][64];
    __shared__ float Bs[16][64];
    const int bm = blockIdx.y * 64, bn = blockIdx.x * 64;
    const int tid = threadIdx.x;
    const int tx = tid & 15, ty = tid >> 4;
    const int am = tid >> 2, ak = (tid & 3) << 2;
    const int bk = tid >> 4, bn4 = (tid & 15) << 2;
    float acc[4][4] = {};
    for (int k0 = 0; k0 < K; k0 += 16) {
        float4 av = make_float4(0.f, 0.f, 0.f, 0.f);
        if (bm + am < M)
            av = *reinterpret_cast<const float4*>(A + (size_t)(bm + am) * lda + k0 + ak);
        As[ak + 0][am] = av.x; As[ak + 1][am] = av.y;
        As[ak + 2][am] = av.z; As[ak + 3][am] = av.w;
        float4 bv;
        const float* wr = W + (size_t)(k0 + bk) * ldb;
        bv.x = (bn + bn4 + 0 < N) ? wr[bn + bn4 + 0] : 0.f;
        bv.y = (bn + bn4 + 1 < N) ? wr[bn + bn4 + 1] : 0.f;
        bv.z = (bn + bn4 + 2 < N) ? wr[bn + bn4 + 2] : 0.f;
        bv.w = (bn + bn4 + 3 < N) ? wr[bn + bn4 + 3] : 0.f;
        Bs[bk][bn4 + 0] = bv.x; Bs[bk][bn4 + 1] = bv.y;
        Bs[bk][bn4 + 2] = bv.z; Bs[bk][bn4 + 3] = bv.w;
        __syncthreads();
        #pragma unroll
        for (int kk = 0; kk < 16; kk++) {
            float af[4], bf[4];
            #pragma unroll
            for (int i = 0; i < 4; i++) af[i] = As[kk][(ty << 2) + i];
            #pragma unroll
            for (int j = 0; j < 4; j++) bf[j] = Bs[kk][(tx << 2) + j];
            #pragma unroll
            for (int i = 0; i < 4; i++)
                #pragma unroll
                for (int j = 0; j < 4; j++)
                    acc[i][j] = fmaf(af[i], bf[j], acc[i][j]);
        }
        __syncthreads();
    }
    #pragma unroll
    for (int i = 0; i < 4; i++) {
        int m = bm + (ty << 2) + i;
        if (m >= M) continue;
        #pragma unroll
        for (int j = 0; j < 4; j++) {
            int n = bn + (tx << 2) + j;
            if (n >= N) continue;
            C[(size_t)m * ldc + n] = acc[i][j] * rmask[m];
        }
    }
}

__global__ void tail_k(float* __restrict__ out, const float* __restrict__ mask, int n) {
    int i = blockIdx.x * blockDim.x + threadIdx.x;
    if (i >= n) return;
    out[i] = (i < NB * TD) ? mask[i] : 0.f;
}

// ---------------- host driver ----------------
extern "C" void kernel_launch(void* const* d_in, const int* in_sizes, int n_in,
                              void* d_out, int out_size) {
    (void)n_in;
    int map[32];
    if (in_sizes[2] == 3 * DM * 2 * DI) {
        for (int i = 0; i < 32; i++) map[i] = i;
    } else {
        const int m[32] = {0, 1,
                           14, 15, 16, 17, 18, 19, 20, 21, 22,
                           2, 3, 4, 5, 6, 7, 8, 9, 10, 11,
                           23, 24, 25, 26, 27, 28, 29, 30, 31,
                           12, 13};
        for (int i = 0; i < 32; i++) map[i] = m[i];
    }
    const int*   text      = (const int*)  d_in[map[0]];
    const float* emb       = (const float*)d_in[map[1]];
    const float* enc_in_w  = (const float*)d_in[map[2]];
    const float* enc_cw    = (const float*)d_in[map[3]];
    const float* enc_cb    = (const float*)d_in[map[4]];
    const float* enc_xpw   = (const float*)d_in[map[5]];
    const float* enc_dtw   = (const float*)d_in[map[6]];
    const float* enc_dtb   = (const float*)d_in[map[7]];
    const float* enc_alog  = (const float*)d_in[map[8]];
    const float* enc_dp    = (const float*)d_in[map[9]];
    const float* enc_ow    = (const float*)d_in[map[10]];
    const float* dp_c1w    = (const float*)d_in[map[11]];
    const float* dp_c1b    = (const float*)d_in[map[12]];
    const float* dp_g1     = (const float*)d_in[map[13]];
    const float* dp_b1     = (const float*)d_in[map[14]];
    const float* dp_c2w    = (const float*)d_in[map[15]];
    const float* dp_c2b    = (const float*)d_in[map[16]];
    const float* dp_g2     = (const float*)d_in[map[17]];
    const float* dp_b2     = (const float*)d_in[map[18]];
    const float* dp_c3w    = (const float*)d_in[map[19]];
    const float* dp_c3b    = (const float*)d_in[map[20]];
    const float* dec_in_w  = (const float*)d_in[map[21]];
    const float* dec_cw    = (const float*)d_in[map[22]];
    const float* dec_cb    = (const float*)d_in[map[23]];
    const float* dec_xpw   = (const float*)d_in[map[24]];
    const float* dec_dtw   = (const float*)d_in[map[25]];
    const float* dec_dtb   = (const float*)d_in[map[26]];
    const float* dec_alog  = (const float*)d_in[map[27]];
    const float* dec_dpv   = (const float*)d_in[map[28]];
    const float* dec_ow    = (const float*)d_in[map[29]];
    const float* norm_g    = (const float*)d_in[map[30]];
    const float* out_w     = (const float*)d_in[map[31]];

    float *x0, *x1, *xz, *u, *xdbl, *part, *delta, *wt, *h1, *h2, *dur, *mask;
    int* idx;
    __nv_bfloat16 *wext, *xe, *ge, *ime;
    cudaGetSymbolAddress((void**)&x0,    g_x0);
    cudaGetSymbolAddress((void**)&x1,    g_x1);
    cudaGetSymbolAddress((void**)&xz,    g_xz);
    cudaGetSymbolAddress((void**)&u,     g_u);
    cudaGetSymbolAddress((void**)&xdbl,  g_xdbl);
    cudaGetSymbolAddress((void**)&part,  g_part);
    cudaGetSymbolAddress((void**)&delta, g_delta);
    cudaGetSymbolAddress((void**)&wt,    g_wt);
    cudaGetSymbolAddress((void**)&h1,    g_h1);
    cudaGetSymbolAddress((void**)&h2,    g_h2);
    cudaGetSymbolAddress((void**)&dur,   g_dur);
    cudaGetSymbolAddress((void**)&idx,   g_idx);
    cudaGetSymbolAddress((void**)&mask,  g_mask);
    cudaGetSymbolAddress((void**)&wext,  g_wext);
    cudaGetSymbolAddress((void**)&xe,    g_xe);
    cudaGetSymbolAddress((void**)&ge,    g_ge);
    cudaGetSymbolAddress((void**)&ime,   g_ime);

    cudaFuncSetAttribute(hmma_k<0, 0>, cudaFuncAttributeMaxDynamicSharedMemorySize, HS);
    cudaFuncSetAttribute(hmma_k<0, 1>, cudaFuncAttributeMaxDynamicSharedMemorySize, HS);
    cudaFuncSetAttribute(hmma_k<2, 0>, cudaFuncAttributeMaxDynamicSharedMemorySize, HS);

    // TC GEMM: C[M,N] = Aext[M,3K] @ W[K,N] (+epilogue / +Cext)
    auto tcgemm = [&](int epi, const __nv_bfloat16* Ae, const float* W, float* C,
                      __nv_bfloat16* Cext, int M, int N, int K,
                      const float* bias, const float* gamma, const float* beta) {
        split_w_k<<<dim3(N / 32, K / 32), dim3(32, 32)>>>(W, wext, K, N);
        dim3 grid(N / 128, M / 128);
        if (epi == 2)
            hmma_k<2, 0><<<grid, 256, HS>>>(Ae, wext, C, nullptr, 3 * K, N, bias, gamma, beta);
        else if (Cext)
            hmma_k<0, 1><<<grid, 256, HS>>>(Ae, wext, C, Cext, 3 * K, N, nullptr, nullptr, nullptr);
        else
            hmma_k<0, 0><<<grid, 256, HS>>>(Ae, wext, C, nullptr, 3 * K, N, nullptr, nullptr, nullptr);
    };

    auto mamba = [&](float* xout, int L, int l,
                     const float* inw, const float* cw, const float* cb,
                     const float* xpw, const float* dtw, const float* dtb,
                     const float* alog, const float* dp, const float* ow) {
        int M = NB * L;
        // in_proj: xe[M,512-ext] @ [512,2048] -> xz (fp32 only)
        tcgemm(0, xe, inw + (size_t)l * DM * 2 * DI, xz, nullptr, M, 2 * DI, DM,
               nullptr, nullptr, nullptr);
        int tot = M * DI;
        dwconv_silu_k<<<(tot + 255) / 256, 256>>>(xz, cw + (size_t)l * DI * 4,
                                                  cb + (size_t)l * DI, u, L);
        // xproj split-K (fp32)
        xp_k<<<dim3(M / 64, KS), 256>>>(u, xpw + (size_t)l * DI * 64, part, M);
        xp_reduce_k<<<(M * 16 + 255) / 256, 256>>>(part, xdbl, M);
        // dt (fp32, K=32)
        gemm64_k<1><<<dim3(DI / 64, M / 64), 256>>>(
            xdbl, dtw + (size_t)l * DTR * DI, delta, DTR, 64, DI, DI,
            dtb + (size_t)l * DI, nullptr, nullptr);
        // scan -> gate-ext
        scan_k<<<(NB * DI * 8 + 127) / 128, 128>>>(xdbl, delta, u, xz,
                                                   alog + (size_t)l * DI * DS,
                                                   dp + (size_t)l * DI, ge, L);
        // out_proj: ge[M,1024-ext] @ [1024,512] -> xout (fp32) + xe (ext for next layer)
        tcgemm(0, ge, ow + (size_t)l * DI * DM, xout, xe, M, DM, DI,
               nullptr, nullptr, nullptr);
    };

    embed_k<<<(ME * DM + 255) / 256, 256>>>(text, emb, x0, xe);

    mamba(x1, TE, 0, enc_in_w, enc_cw, enc_cb, enc_xpw, enc_dtw, enc_dtb, enc_alog, enc_dp, enc_ow);
    mamba(x0, TE, 1, enc_in_w, enc_cw, enc_cb, enc_xpw, enc_dtw, enc_dtb, enc_alog, enc_dp, enc_ow);
    mamba(x1, TE, 2, enc_in_w, enc_cw, enc_cb, enc_xpw, enc_dtw, enc_dtb, enc_alog, enc_dp, enc_ow);

    // duration predictor on x1 (tensor-core convs; im2col writes ext directly)
    wt_k<<<(DM * DM * 3 + 255) / 256, 256>>>(dp_c1w, wt);
    im2col_k<<<(ME * DM * 3 + 255) / 256, 256>>>(x1, ime);
    tcgemm(2, ime, wt, h1, nullptr, ME, DM, 3 * DM, dp_c1b, dp_g1, dp_b1);
    wt_k<<<(DM * DM * 3 + 255) / 256, 256>>>(dp_c2w, wt);
    im2col_k<<<(ME * DM * 3 + 255) / 256, 256>>>(h1, ime);
    tcgemm(2, ime, wt, h2, nullptr, ME, DM, 3 * DM, dp_c2b, dp_g2, dp_b2);
    dur_k<<<(ME * 32 + 255) / 256, 256>>>(h2, dp_c3w, dp_c3b, dur);

    expand_k<<<NB, TE>>>(dur, idx, mask);
    gather_k<<<(MD * DM + 255) / 256, 256>>>(x1, idx, mask, xe);

    mamba(x1, TD, 0, dec_in_w, dec_cw, dec_cb, dec_xpw, dec_dtw, dec_dtb, dec_alog, dec_dpv, dec_ow);
    mamba(x0, TD, 1, dec_in_w, dec_cw, dec_cb, dec_xpw, dec_dtw, dec_dtb, dec_alog, dec_dpv, dec_ow);
    mamba(x1, TD, 2, dec_in_w, dec_cw, dec_cb, dec_xpw, dec_dtw, dec_dtb, dec_alog, dec_dpv, dec_ow);

    rmsnorm_k<<<MD, 128>>>(x1, norm_g, x0);
    melgemm_k<<<dim3((NM + 63) / 64, MD / 64), 256>>>(
        x0, out_w, (float*)d_out, MD, NM, DM, DM, NM, NM, mask);

    int melN = MD * NM;
    if (out_size > melN) {
        int n = out_size - melN;
        tail_k<<<(n + 255) / 256, 256>>>((float*)d_out + melN, mask, n);
    }
}

// round 8
// speedup vs baseline: 1.2834x; 1.2219x over previous
#include <cuda_runtime.h>
#include <cuda_bf16.h>
#include <math.h>
#include <stdint.h>

namespace {
constexpr int NB = 4, TE = 256, TD = 512, DM = 512, DI = 1024, DS = 16, DTR = 32, NM = 80;
constexpr int ME = NB * TE;
constexpr int MD = NB * TD;
constexpr int KS = 8;          // xproj split-K factor
constexpr int ST = 4;          // cp.async stages
constexpr int A_STAGE = 128 * 80;              // bytes per A stage
}

// ---------------- scratch ----------------
__device__ float g_x0[MD * DM];
__device__ float g_x1[MD * DM];
__device__ float g_xz[MD * 2 * DI];
__device__ float g_u[MD * DI];
__device__ float g_xdbl[MD * 64];
__device__ float g_part[KS * MD * 64];   // 1M floats, reused as split-K partial buffer
__device__ float g_delta[MD * DI];
__device__ float g_wt[DM * 3 * DM];
__device__ float g_h1[ME * DM];
__device__ float g_h2[ME * DM];
__device__ float g_dur[ME];
__device__ int   g_idx[NB * TD];
__device__ float g_mask[NB * TD];
__device__ uint4 g_wext[393216];
__device__ uint4 g_xe[393216];
__device__ uint4 g_ge[786432];
__device__ uint4 g_ime[589824];

__device__ __forceinline__ float softplus_f(float x) {
    return x > 0.f ? x + log1pf(expf(-x)) : log1pf(expf(x));
}
__device__ __forceinline__ float silu_f(float x) {
    return x / (1.f + expf(-x));
}
__device__ __forceinline__ uint32_t smem_u32(const void* p) {
    uint32_t a;
    asm("{ .reg .u64 t; cvta.to.shared.u64 t, %1; cvt.u32.u64 %0, t; }" : "=r"(a) : "l"(p));
    return a;
}
#define CP_ASYNC16(dst, src) asm volatile("cp.async.cg.shared.global [%0], [%1], 16;" :: "r"(dst), "l"(src))
#define CP_COMMIT()          asm volatile("cp.async.commit_group;")
#define CP_WAIT(n)           asm volatile("cp.async.wait_group %0;" :: "n"(n))

__device__ __forceinline__ void write_aext(__nv_bfloat16* e, size_t row, int K, int k, float a) {
    __nv_bfloat16 hi = __float2bfloat16_rn(a);
    __nv_bfloat16 lo = __float2bfloat16_rn(a - __bfloat162float(hi));
    size_t base = row * (size_t)(3 * K);
    e[base + k] = hi;
    e[base + K + k] = hi;
    e[base + 2 * K + k] = lo;
}

// ================= weight split (B ext: [N][3K], row n = [hi|lo|hi]) =================
__global__ void split_w_k(const float* __restrict__ W, __nv_bfloat16* __restrict__ out,
                          int K, int N) {
    __shared__ float tile[32][33];
    int n0 = blockIdx.x * 32, k0 = blockIdx.y * 32;
    int tx = threadIdx.x, ty = threadIdx.y;
    tile[ty][tx] = W[(size_t)(k0 + ty) * N + n0 + tx];
    __syncthreads();
    int n = n0 + ty, k = k0 + tx;
    float a = tile[tx][ty];
    __nv_bfloat16 hi = __float2bfloat16_rn(a);
    __nv_bfloat16 lo = __float2bfloat16_rn(a - __bfloat162float(hi));
    size_t base = (size_t)n * 3 * K;
    out[base + k] = hi;
    out[base + K + k] = lo;
    out[base + 2 * K + k] = hi;
}
// padded variant: logical N columns, padded to Npad rows of ext (zeros beyond N)
__global__ void split_w_pad_k(const float* __restrict__ W, __nv_bfloat16* __restrict__ out,
                              int K, int N, int Npad) {
    __shared__ float tile[32][33];
    int n0 = blockIdx.x * 32, k0 = blockIdx.y * 32;
    int tx = threadIdx.x, ty = threadIdx.y;
    tile[ty][tx] = (n0 + tx < N) ? W[(size_t)(k0 + ty) * N + n0 + tx] : 0.f;
    __syncthreads();
    int n = n0 + ty, k = k0 + tx;
    if (n >= Npad) return;
    float a = tile[tx][ty];
    __nv_bfloat16 hi = __float2bfloat16_rn(a);
    __nv_bfloat16 lo = __float2bfloat16_rn(a - __bfloat162float(hi));
    size_t base = (size_t)n * 3 * K;
    out[base + k] = hi;
    out[base + K + k] = lo;
    out[base + 2 * K + k] = hi;
}

// ================= HMMA bf16 GEMM, cp.async pipeline, templated tile width =================
// BN: 128 or 64. EPI: 0 none. WEXT: also write Cext [M][3N]. SPLIT: raw partials to C+z*MN.
template<int BN, int EPI, int WEXT, int SPLIT>
__global__ __launch_bounds__(256) void hmma_k(
    const __nv_bfloat16* __restrict__ Ae, const __nv_bfloat16* __restrict__ Be,
    float* __restrict__ C, __nv_bfloat16* __restrict__ Cext,
    int K3row, int K3c, int N, int MN,
    const float* __restrict__ bias, const float* __restrict__ gamma,
    const float* __restrict__ beta)
{
    constexpr int B_STAGE = BN * 80;
    constexpr int NT = BN / 32;
    extern __shared__ char dsm[];
    const uint32_t saA = smem_u32(dsm);
    const uint32_t saB = saA + ST * A_STAGE;

    const int tid = threadIdx.x, lane = tid & 31, w = tid >> 5;
    const int wm = w & 1, wn = w >> 1;
    const int bm = blockIdx.y * 128, bn = blockIdx.x * BN;
    const int z = SPLIT ? blockIdx.z : 0;
    const size_t arow = (size_t)K3row * 2;

    const char* Ag = (const char*)Ae + (size_t)bm * arow + (size_t)z * K3c * 2;
    const char* Bg = (const char*)Be + (size_t)bn * arow + (size_t)z * K3c * 2;
    const int ldr = tid >> 2, lds = tid & 3;

    auto issue = [&](int kc, int s) {
        const size_t go = (size_t)ldr * arow + (size_t)kc * 64 + lds * 16;
        const uint32_t da = saA + s * A_STAGE + ldr * 80 + lds * 16;
        CP_ASYNC16(da, Ag + go);
        CP_ASYNC16(da + 64 * 80, Ag + go + (size_t)64 * arow);
        const uint32_t db = saB + s * B_STAGE + ldr * 80 + lds * 16;
        CP_ASYNC16(db, Bg + go);
        if (BN == 128) CP_ASYNC16(db + 64 * 80, Bg + go + (size_t)64 * arow);
    };

    float acc[4][NT][4];
    #pragma unroll
    for (int i = 0; i < 4; i++)
        #pragma unroll
        for (int j = 0; j < NT; j++)
            #pragma unroll
            for (int e = 0; e < 4; e++) acc[i][j][e] = 0.f;

    const int a_row = wm * 64 + (lane & 15);
    const int a_kof = (lane >> 4) * 8;
    const int bl = lane & 15;
    const int b_row = wn * (BN / 4) + (bl & 7);
    const int b_kof = (bl >> 3) * 8;

    auto compute = [&](int s) {
        const uint32_t abase = saA + s * A_STAGE;
        const uint32_t bbase = saB + s * B_STAGE;
        #pragma unroll
        for (int ks = 0; ks < 2; ks++) {
            uint32_t af[4][4];
            #pragma unroll
            for (int mt = 0; mt < 4; mt++) {
                uint32_t addr = abase + (a_row + mt * 16) * 80 + (a_kof + ks * 16) * 2;
                asm volatile("ldmatrix.sync.aligned.m8n8.x4.shared.b16 {%0,%1,%2,%3}, [%4];"
                    : "=r"(af[mt][0]), "=r"(af[mt][1]), "=r"(af[mt][2]), "=r"(af[mt][3])
                    : "r"(addr));
            }
            uint32_t bf[NT][2];
            #pragma unroll
            for (int nt = 0; nt < NT; nt++) {
                uint32_t addr = bbase + (b_row + nt * 8) * 80 + (b_kof + ks * 16) * 2;
                asm volatile("ldmatrix.sync.aligned.m8n8.x2.shared.b16 {%0,%1}, [%2];"
                    : "=r"(bf[nt][0]), "=r"(bf[nt][1])
                    : "r"(addr));
            }
            #pragma unroll
            for (int mt = 0; mt < 4; mt++)
                #pragma unroll
                for (int nt = 0; nt < NT; nt++) {
                    asm volatile(
                        "mma.sync.aligned.m16n8k16.row.col.f32.bf16.bf16.f32 "
                        "{%0,%1,%2,%3}, {%4,%5,%6,%7}, {%8,%9}, {%0,%1,%2,%3};"
                        : "+f"(acc[mt][nt][0]), "+f"(acc[mt][nt][1]),
                          "+f"(acc[mt][nt][2]), "+f"(acc[mt][nt][3])
                        : "r"(af[mt][0]), "r"(af[mt][1]), "r"(af[mt][2]), "r"(af[mt][3]),
                          "r"(bf[nt][0]), "r"(bf[nt][1]));
                }
        }
    };

    const int NC = K3c / 32;
    #pragma unroll
    for (int s = 0; s < ST - 1; s++) { if (s < NC) issue(s, s); CP_COMMIT(); }
    for (int kc = 0; kc < NC; kc++) {
        CP_WAIT(ST - 2);
        __syncthreads();
        compute(kc & (ST - 1));
        int nx = kc + ST - 1;
        if (nx < NC) issue(nx, nx & (ST - 1));
        CP_COMMIT();
    }

    // epilogue
    const int tq = lane >> 2, tr = lane & 3;
    float* Cz = SPLIT ? (C + (size_t)z * MN) : C;
    #pragma unroll
    for (int mt = 0; mt < 4; mt++) {
        #pragma unroll
        for (int nt = 0; nt < NT; nt++) {
            int row0 = bm + wm * 64 + mt * 16 + tq;
            int col = bn + wn * (BN / 4) + nt * 8 + tr * 2;
            float v[4] = {acc[mt][nt][0], acc[mt][nt][1], acc[mt][nt][2], acc[mt][nt][3]};
            *reinterpret_cast<float2*>(Cz + (size_t)row0 * N + col) = make_float2(v[0], v[1]);
            *reinterpret_cast<float2*>(Cz + (size_t)(row0 + 8) * N + col) = make_float2(v[2], v[3]);
            if (WEXT && !SPLIT) {
                #pragma unroll
                for (int h = 0; h < 2; h++) {
                    float a0 = v[h * 2], a1 = v[h * 2 + 1];
                    __nv_bfloat16 h0 = __float2bfloat16_rn(a0), h1 = __float2bfloat16_rn(a1);
                    __nv_bfloat16 l0 = __float2bfloat16_rn(a0 - __bfloat162float(h0));
                    __nv_bfloat16 l1 = __float2bfloat16_rn(a1 - __bfloat162float(h1));
                    size_t base = (size_t)(row0 + h * 8) * (3 * N);
                    __nv_bfloat162 hv = __halves2bfloat162(h0, h1);
                    __nv_bfloat162 lv = __halves2bfloat162(l0, l1);
                    *reinterpret_cast<__nv_bfloat162*>(Cext + base + col) = hv;
                    *reinterpret_cast<__nv_bfloat162*>(Cext + base + N + col) = hv;
                    *reinterpret_cast<__nv_bfloat162*>(Cext + base + 2 * N + col) = lv;
                }
            }
        }
    }
}

// ============ split-K combine: C = P[0] + P[1] with fused epilogue ============
// EPI: 0=none, 2=relu(+bias)*bn+beta, 3=mask-mel (guard col<Nreal, *rmask, ldc=Nreal)
template<int EPI, int WEXT>
__global__ void combine_k(const float* __restrict__ P, int MN, int N, int Nreal,
                          float* __restrict__ C, __nv_bfloat16* __restrict__ Cext,
                          const float* __restrict__ bias, const float* __restrict__ gamma,
                          const float* __restrict__ beta, const float* __restrict__ rmask)
{
    int i = blockIdx.x * blockDim.x + threadIdx.x;
    if (i >= MN) return;
    int row = i / N, col = i % N;
    float v = P[i] + P[MN + i];
    if (EPI == 2)
        v = fmaxf(v + bias[col], 0.f) * (gamma[col] * rsqrtf(1.f + 1e-5f)) + beta[col];
    if (EPI == 3) {
        if (col >= Nreal) return;
        C[(size_t)row * Nreal + col] = v * rmask[row];
        return;
    }
    C[i] = v;
    if (WEXT) write_aext(Cext, row, N, col, v);
}

// ---------------- embedding: fp32 + x-ext ----------------
__global__ void embed_k(const int* __restrict__ text, const float* __restrict__ emb,
                        float* __restrict__ out, __nv_bfloat16* __restrict__ oute) {
    int i = blockIdx.x * blockDim.x + threadIdx.x;
    if (i >= ME * DM) return;
    int c = i % DM;
    int r = i / DM;
    float v = emb[text[r] * DM + c];
    out[i] = v;
    write_aext(oute, r, DM, c, v);
}

// ============ gemm64 (fp32): dt projection (K=32) ============
template<int EPI>
__global__ __launch_bounds__(256) void gemm64_k(
    const float* __restrict__ A, const float* __restrict__ W, float* __restrict__ C,
    int K, int lda, int ldb, int ldc,
    const float* __restrict__ bias)
{
    __shared__ float As[2][16][64];
    __shared__ float Bs[2][16][64];
    const int tid = threadIdx.x;
    const int tx = tid & 15, ty = tid >> 4;
    const int bm = blockIdx.y * 64, bn = blockIdx.x * 64;
    const int ar = tid >> 2, ac = (tid & 3) << 2;
    const int br = tid >> 4, bc = (tid & 15) << 2;
    const float* Ag = A + (size_t)(bm + ar) * lda + ac;
    const float* Wg = W + bn + bc;

    float4 ap, bp;
    auto ld = [&](int k0) {
        ap = *reinterpret_cast<const float4*>(Ag + k0);
        bp = *reinterpret_cast<const float4*>(Wg + (size_t)(k0 + br) * ldb);
    };
    auto st = [&](int buf) {
        As[buf][ac + 0][ar] = ap.x; As[buf][ac + 1][ar] = ap.y;
        As[buf][ac + 2][ar] = ap.z; As[buf][ac + 3][ar] = ap.w;
        *reinterpret_cast<float4*>(&Bs[buf][br][bc]) = bp;
    };

    float acc[4][4] = {};
    const int KB = K / 16;
    ld(0); st(0); __syncthreads();
    for (int kb = 0; kb < KB; kb++) {
        const int cur = kb & 1;
        if (kb + 1 < KB) ld((kb + 1) * 16);
        #pragma unroll
        for (int kk = 0; kk < 16; kk++) {
            float a[4], b[4];
            *reinterpret_cast<float4*>(a) = *reinterpret_cast<const float4*>(&As[cur][kk][ty * 4]);
            *reinterpret_cast<float4*>(b) = *reinterpret_cast<const float4*>(&Bs[cur][kk][tx * 4]);
            #pragma unroll
            for (int i = 0; i < 4; i++)
                #pragma unroll
                for (int j = 0; j < 4; j++)
                    acc[i][j] = fmaf(a[i], b[j], acc[i][j]);
        }
        if (kb + 1 < KB) st(1 - cur);
        __syncthreads();
    }
    #pragma unroll
    for (int i = 0; i < 4; i++) {
        const int m = bm + ty * 4 + i;
        const int n0 = bn + tx * 4;
        float4 v;
        float* pv = &v.x;
        #pragma unroll
        for (int q = 0; q < 4; q++) {
            float x = acc[i][q];
            if (EPI == 1) x = softplus_f(x + bias[n0 + q]);
            pv[q] = x;
        }
        *reinterpret_cast<float4*>(C + (size_t)m * ldc + n0) = v;
    }
}

// ============ xproj split-K (fp32) ============
__global__ __launch_bounds__(256) void xp_k(
    const float* __restrict__ A, const float* __restrict__ W, float* __restrict__ P, int M)
{
    __shared__ float As[2][16][64];
    __shared__ float Bs[2][16][64];
    const int tid = threadIdx.x;
    const int tx = tid & 15, ty = tid >> 4;
    const int bm = blockIdx.x * 64;
    const int kz = blockIdx.y;
    const int kbase = kz * (DI / KS);
    const int ar = tid >> 2, ac = (tid & 3) << 2;
    const int br = tid >> 4, bc = (tid & 15) << 2;
    const float* Ag = A + (size_t)(bm + ar) * DI + kbase + ac;
    const float* Wg = W + (size_t)kbase * 64 + bc;

    float4 ap, bp;
    auto ld = [&](int k0) {
        ap = *reinterpret_cast<const float4*>(Ag + k0);
        bp = *reinterpret_cast<const float4*>(Wg + (size_t)(k0 + br) * 64);
    };
    auto st = [&](int buf) {
        As[buf][ac + 0][ar] = ap.x; As[buf][ac + 1][ar] = ap.y;
        As[buf][ac + 2][ar] = ap.z; As[buf][ac + 3][ar] = ap.w;
        *reinterpret_cast<float4*>(&Bs[buf][br][bc]) = bp;
    };

    float acc[4][4] = {};
    const int KB = (DI / KS) / 16;
    ld(0); st(0); __syncthreads();
    for (int kb = 0; kb < KB; kb++) {
        const int cur = kb & 1;
        if (kb + 1 < KB) ld((kb + 1) * 16);
        #pragma unroll
        for (int kk = 0; kk < 16; kk++) {
            float a[4], b[4];
            *reinterpret_cast<float4*>(a) = *reinterpret_cast<const float4*>(&As[cur][kk][ty * 4]);
            *reinterpret_cast<float4*>(b) = *reinterpret_cast<const float4*>(&Bs[cur][kk][tx * 4]);
            #pragma unroll
            for (int i = 0; i < 4; i++)
                #pragma unroll
                for (int j = 0; j < 4; j++)
                    acc[i][j] = fmaf(a[i], b[j], acc[i][j]);
        }
        if (kb + 1 < KB) st(1 - cur);
        __syncthreads();
    }
    float* Pg = P + ((size_t)kz * M + bm) * 64;
    #pragma unroll
    for (int i = 0; i < 4; i++) {
        float4 v = make_float4(acc[i][0], acc[i][1], acc[i][2], acc[i][3]);
        *reinterpret_cast<float4*>(Pg + (size_t)(ty * 4 + i) * 64 + tx * 4) = v;
    }
}

__global__ void xp_reduce_k(const float* __restrict__ P, float* __restrict__ out, int M) {
    int i = blockIdx.x * blockDim.x + threadIdx.x;
    if (i >= M * 16) return;
    float4 s = make_float4(0.f, 0.f, 0.f, 0.f);
    #pragma unroll
    for (int z = 0; z < KS; z++) {
        float4 v = *reinterpret_cast<const float4*>(P + ((size_t)z * M * 16 + i) * 4);
        s.x += v.x; s.y += v.y; s.z += v.z; s.w += v.w;
    }
    *reinterpret_cast<float4*>(out + (size_t)i * 4) = s;
}

// ---------------- depthwise causal conv (K=4) + SiLU ----------------
__global__ void dwconv_silu_k(const float* __restrict__ xz, const float* __restrict__ w,
                              const float* __restrict__ bcv, float* __restrict__ u, int L) {
    int i = blockIdx.x * blockDim.x + threadIdx.x;
    int total = NB * L * DI;
    if (i >= total) return;
    int d = i % DI;
    int bt = i / DI;
    int t = bt % L;
    int bb = bt / L;
    float acc = bcv[d];
    const float* wr = w + d * 4;
    #pragma unroll
    for (int k = 0; k < 4; k++) {
        int ts = t - 3 + k;
        if (ts >= 0)
            acc = fmaf(wr[k], xz[((size_t)(bb * L + ts)) * 2048 + d], acc);
    }
    u[i] = silu_f(acc);
}

// ---------------- selective scan: 8 threads/(b,d), writes gate-ext ----------------
__global__ void scan_k(const float* __restrict__ xdbl, const float* __restrict__ delta,
                       const float* __restrict__ u, const float* __restrict__ xz,
                       const float* __restrict__ Alog, const float* __restrict__ Dp,
                       __nv_bfloat16* __restrict__ ge, int L) {
    int gt = blockIdx.x * blockDim.x + threadIdx.x;
    if (gt >= NB * DI * 8) return;
    int lane = gt & 7;
    int gid = gt >> 3;
    int d = gid % DI;
    int bb = gid / DI;
    float a0 = -expf(Alog[d * DS + lane * 2 + 0]);
    float a1 = -expf(Alog[d * DS + lane * 2 + 1]);
    float Dd = Dp[d];
    float h0 = 0.f, h1 = 0.f;

    float dl, ut, rs;
    float2 Bv, Cv;
    auto loadt = [&](int t, float& dl_, float& ut_, float2& B_, float2& C_, float& rs_) {
        size_t row = (size_t)bb * L + t;
        dl_ = delta[row * DI + d];
        ut_ = u[row * DI + d];
        const float* xd = xdbl + row * 64;
        B_ = *reinterpret_cast<const float2*>(xd + 32 + lane * 2);
        C_ = *reinterpret_cast<const float2*>(xd + 48 + lane * 2);
        rs_ = xz[row * 2048 + 1024 + d];
    };
    loadt(0, dl, ut, Bv, Cv, rs);
    for (int t = 0; t < L; t++) {
        float dl2, ut2, rs2;
        float2 Bv2, Cv2;
        if (t + 1 < L) loadt(t + 1, dl2, ut2, Bv2, Cv2, rs2);
        float du = dl * ut;
        h0 = fmaf(__expf(dl * a0), h0, du * Bv.x);
        h1 = fmaf(__expf(dl * a1), h1, du * Bv.y);
        float y = h0 * Cv.x + h1 * Cv.y;
        y += __shfl_xor_sync(0xffffffffu, y, 1);
        y += __shfl_xor_sync(0xffffffffu, y, 2);
        y += __shfl_xor_sync(0xffffffffu, y, 4);
        if (lane == 0) {
            size_t row = (size_t)bb * L + t;
            float g = (y + ut * Dd) * silu_f(rs);
            write_aext(ge, row, DI, d, g);
        }
        dl = dl2; ut = ut2; Bv = Bv2; Cv = Cv2; rs = rs2;
    }
}

// ---------------- duration predictor helpers ----------------
__global__ void wt_k(const float* __restrict__ w, float* __restrict__ wt) {
    int i = blockIdx.x * blockDim.x + threadIdx.x;
    if (i >= DM * DM * 3) return;
    int k = i % 3;
    int c = (i / 3) % DM;
    int d = i / (3 * DM);
    wt[(size_t)(k * DM + c) * DM + d] = w[i];
}
__global__ void im2col_k(const float* __restrict__ src, __nv_bfloat16* __restrict__ dste) {
    int i = blockIdx.x * blockDim.x + threadIdx.x;
    if (i >= ME * DM * 3) return;
    int c = i % DM;
    int k = (i / DM) % 3;
    int r = i / (DM * 3);
    int t = r % TE;
    int ts = t - 1 + k;
    float v = 0.f;
    if (ts >= 0 && ts < TE) v = src[(size_t)(r - t + ts) * DM + c];
    write_aext(dste, r, 3 * DM, k * DM + c, v);
}
__global__ void dur_k(const float* __restrict__ h2, const float* __restrict__ w3,
                      const float* __restrict__ b3, float* __restrict__ dur) {
    int warp = (blockIdx.x * blockDim.x + threadIdx.x) >> 5;
    int lane = threadIdx.x & 31;
    if (warp >= ME) return;
    const float* hr = h2 + (size_t)warp * DM;
    float s = 0.f;
    for (int c = lane; c < DM; c += 32) s = fmaf(hr[c], w3[c], s);
    #pragma unroll
    for (int o = 16; o; o >>= 1) s += __shfl_xor_sync(0xffffffffu, s, o);
    if (lane == 0) dur[warp] = softplus_f(s + b3[0]);
}

// ---------------- length regulator ----------------
__global__ void expand_k(const float* __restrict__ dur, int* __restrict__ idx,
                         float* __restrict__ mask) {
    __shared__ float ends[TE];
    int bb = blockIdx.x;
    int t = threadIdx.x;
    ends[t] = rintf(fmaxf(dur[bb * TE + t], 0.f));
    __syncthreads();
    if (t == 0) {
        float s = 0.f;
        for (int i = 0; i < TE; i++) { s += ends[i]; ends[i] = s; }
    }
    __syncthreads();
    float total = ends[TE - 1];
    for (int tp = t; tp < TD; tp += TE) {
        float fp = (float)tp;
        int lo = 0, hi = TE;
        while (lo < hi) { int mid = (lo + hi) >> 1; if (ends[mid] <= fp) lo = mid + 1; else hi = mid; }
        int id = lo < TE - 1 ? lo : TE - 1;
        idx[bb * TD + tp] = id;
        mask[bb * TD + tp] = fp < total ? 1.f : 0.f;
    }
}
__global__ void gather_k(const float* __restrict__ enc, const int* __restrict__ idx,
                         const float* __restrict__ mask, __nv_bfloat16* __restrict__ oute) {
    int i = blockIdx.x * blockDim.x + threadIdx.x;
    if (i >= MD * DM) return;
    int c = i % DM;
    int r = i / DM;
    int bb = r / TD;
    float v = enc[(size_t)(bb * TE + idx[r]) * DM + c] * mask[r];
    write_aext(oute, r, DM, c, v);
}

// ---------------- rmsnorm -> ext only ----------------
__global__ void rmsnorm_k(const float* __restrict__ x, const float* __restrict__ g,
                          __nv_bfloat16* __restrict__ oute) {
    int r = blockIdx.x;
    const float* xr = x + (size_t)r * DM;
    float s = 0.f;
    for (int c = threadIdx.x; c < DM; c += blockDim.x) { float v = xr[c]; s = fmaf(v, v, s); }
    __shared__ float red[4];
    #pragma unroll
    for (int o = 16; o; o >>= 1) s += __shfl_xor_sync(0xffffffffu, s, o);
    int w = threadIdx.x >> 5;
    if ((threadIdx.x & 31) == 0) red[w] = s;
    __syncthreads();
    if (threadIdx.x == 0) red[0] = red[0] + red[1] + red[2] + red[3];
    __syncthreads();
    float scale = rsqrtf(red[0] / (float)DM + 1e-6f);
    for (int c = threadIdx.x; c < DM; c += blockDim.x)
        write_aext(oute, r, DM, c, xr[c] * scale * g[c]);
}

__global__ void tail_k(float* __restrict__ out, const float* __restrict__ mask, int n) {
    int i = blockIdx.x * blockDim.x + threadIdx.x;
    if (i >= n) return;
    out[i] = (i < NB * TD) ? mask[i] : 0.f;
}

// ---------------- host driver ----------------
extern "C" void kernel_launch(void* const* d_in, const int* in_sizes, int n_in,
                              void* d_out, int out_size) {
    (void)n_in;
    int map[32];
    if (in_sizes[2] == 3 * DM * 2 * DI) {
        for (int i = 0; i < 32; i++) map[i] = i;
    } else {
        const int m[32] = {0, 1,
                           14, 15, 16, 17, 18, 19, 20, 21, 22,
                           2, 3, 4, 5, 6, 7, 8, 9, 10, 11,
                           23, 24, 25, 26, 27, 28, 29, 30, 31,
                           12, 13};
        for (int i = 0; i < 32; i++) map[i] = m[i];
    }
    const int*   text      = (const int*)  d_in[map[0]];
    const float* emb       = (const float*)d_in[map[1]];
    const float* enc_in_w  = (const float*)d_in[map[2]];
    const float* enc_cw    = (const float*)d_in[map[3]];
    const float* enc_cb    = (const float*)d_in[map[4]];
    const float* enc_xpw   = (const float*)d_in[map[5]];
    const float* enc_dtw   = (const float*)d_in[map[6]];
    const float* enc_dtb   = (const float*)d_in[map[7]];
    const float* enc_alog  = (const float*)d_in[map[8]];
    const float* enc_dp    = (const float*)d_in[map[9]];
    const float* enc_ow    = (const float*)d_in[map[10]];
    const float* dp_c1w    = (const float*)d_in[map[11]];
    const float* dp_c1b    = (const float*)d_in[map[12]];
    const float* dp_g1     = (const float*)d_in[map[13]];
    const float* dp_b1     = (const float*)d_in[map[14]];
    const float* dp_c2w    = (const float*)d_in[map[15]];
    const float* dp_c2b    = (const float*)d_in[map[16]];
    const float* dp_g2     = (const float*)d_in[map[17]];
    const float* dp_b2     = (const float*)d_in[map[18]];
    const float* dp_c3w    = (const float*)d_in[map[19]];
    const float* dp_c3b    = (const float*)d_in[map[20]];
    const float* dec_in_w  = (const float*)d_in[map[21]];
    const float* dec_cw    = (const float*)d_in[map[22]];
    const float* dec_cb    = (const float*)d_in[map[23]];
    const float* dec_xpw   = (const float*)d_in[map[24]];
    const float* dec_dtw   = (const float*)d_in[map[25]];
    const float* dec_dtb   = (const float*)d_in[map[26]];
    const float* dec_alog  = (const float*)d_in[map[27]];
    const float* dec_dpv   = (const float*)d_in[map[28]];
    const float* dec_ow    = (const float*)d_in[map[29]];
    const float* norm_g    = (const float*)d_in[map[30]];
    const float* out_w     = (const float*)d_in[map[31]];

    float *x0, *x1, *xz, *u, *xdbl, *part, *delta, *wt, *h1, *h2, *dur, *mask;
    int* idx;
    __nv_bfloat16 *wext, *xe, *ge, *ime;
    cudaGetSymbolAddress((void**)&x0,    g_x0);
    cudaGetSymbolAddress((void**)&x1,    g_x1);
    cudaGetSymbolAddress((void**)&xz,    g_xz);
    cudaGetSymbolAddress((void**)&u,     g_u);
    cudaGetSymbolAddress((void**)&xdbl,  g_xdbl);
    cudaGetSymbolAddress((void**)&part,  g_part);
    cudaGetSymbolAddress((void**)&delta, g_delta);
    cudaGetSymbolAddress((void**)&wt,    g_wt);
    cudaGetSymbolAddress((void**)&h1,    g_h1);
    cudaGetSymbolAddress((void**)&h2,    g_h2);
    cudaGetSymbolAddress((void**)&dur,   g_dur);
    cudaGetSymbolAddress((void**)&idx,   g_idx);
    cudaGetSymbolAddress((void**)&mask,  g_mask);
    cudaGetSymbolAddress((void**)&wext,  g_wext);
    cudaGetSymbolAddress((void**)&xe,    g_xe);
    cudaGetSymbolAddress((void**)&ge,    g_ge);
    cudaGetSymbolAddress((void**)&ime,   g_ime);

    constexpr int HS128 = ST * (A_STAGE + 128 * 80);   // 81920
    constexpr int HS64  = ST * (A_STAGE + 64 * 80);    // 61440
    cudaFuncSetAttribute(hmma_k<128, 0, 0, 0>, cudaFuncAttributeMaxDynamicSharedMemorySize, HS128);
    cudaFuncSetAttribute(hmma_k<64, 0, 1, 0>,  cudaFuncAttributeMaxDynamicSharedMemorySize, HS64);
    cudaFuncSetAttribute(hmma_k<64, 0, 0, 1>,  cudaFuncAttributeMaxDynamicSharedMemorySize, HS64);

    auto mamba = [&](float* xout, bool wext_out, int L, int l,
                     const float* inw, const float* cw, const float* cb,
                     const float* xpw, const float* dtw, const float* dtb,
                     const float* alog, const float* dp, const float* ow) {
        int M = NB * L;
        // in_proj: xe[M,512-ext] @ [512,2048] -> xz
        split_w_k<<<dim3(2 * DI / 32, DM / 32), dim3(32, 32)>>>(inw + (size_t)l * DM * 2 * DI, wext, DM, 2 * DI);
        hmma_k<128, 0, 0, 0><<<dim3(2 * DI / 128, M / 128), 256, HS128>>>(
            xe, wext, xz, nullptr, 3 * DM, 3 * DM, 2 * DI, 0, nullptr, nullptr, nullptr);
        int tot = M * DI;
        dwconv_silu_k<<<(tot + 255) / 256, 256>>>(xz, cw + (size_t)l * DI * 4,
                                                  cb + (size_t)l * DI, u, L);
        xp_k<<<dim3(M / 64, KS), 256>>>(u, xpw + (size_t)l * DI * 64, part, M);
        xp_reduce_k<<<(M * 16 + 255) / 256, 256>>>(part, xdbl, M);
        gemm64_k<1><<<dim3(DI / 64, M / 64), 256>>>(
            xdbl, dtw + (size_t)l * DTR * DI, delta, DTR, 64, DI, DI, dtb + (size_t)l * DI);
        scan_k<<<(NB * DI * 8 + 127) / 128, 128>>>(xdbl, delta, u, xz,
                                                   alog + (size_t)l * DI * DS,
                                                   dp + (size_t)l * DI, ge, L);
        // out_proj: ge[M,1024-ext] @ [1024,512]
        split_w_k<<<dim3(DM / 32, DI / 32), dim3(32, 32)>>>(ow + (size_t)l * DI * DM, wext, DI, DM);
        if (M >= 2048) {
            // dec: direct, grid 8x16=128
            hmma_k<64, 0, 1, 0><<<dim3(DM / 64, M / 128), 256, HS64>>>(
                ge, wext, xout, xe, 3 * DI, 3 * DI, DM, 0, nullptr, nullptr, nullptr);
        } else {
            // enc: split-K=2, grid 8x8x2=128, combine writes fp32 + xe
            int MN = M * DM;
            hmma_k<64, 0, 0, 1><<<dim3(DM / 64, M / 128, 2), 256, HS64>>>(
                ge, wext, part, nullptr, 3 * DI, 3 * DI / 2, DM, MN, nullptr, nullptr, nullptr);
            if (wext_out)
                combine_k<0, 1><<<(MN + 255) / 256, 256>>>(part, MN, DM, DM, xout, xe,
                                                           nullptr, nullptr, nullptr, nullptr);
            else
                combine_k<0, 0><<<(MN + 255) / 256, 256>>>(part, MN, DM, DM, xout, nullptr,
                                                           nullptr, nullptr, nullptr, nullptr);
        }
    };

    embed_k<<<(ME * DM + 255) / 256, 256>>>(text, emb, x0, xe);

    mamba(x1, true, TE, 0, enc_in_w, enc_cw, enc_cb, enc_xpw, enc_dtw, enc_dtb, enc_alog, enc_dp, enc_ow);
    mamba(x0, true, TE, 1, enc_in_w, enc_cw, enc_cb, enc_xpw, enc_dtw, enc_dtb, enc_alog, enc_dp, enc_ow);
    mamba(x1, true, TE, 2, enc_in_w, enc_cw, enc_cb, enc_xpw, enc_dtw, enc_dtb, enc_alog, enc_dp, enc_ow);

    // duration predictor (split-K=2 TC convs)
    {
        int MN = ME * DM;
        wt_k<<<(DM * DM * 3 + 255) / 256, 256>>>(dp_c1w, wt);
        im2col_k<<<(ME * DM * 3 + 255) / 256, 256>>>(x1, ime);
        split_w_k<<<dim3(DM / 32, 3 * DM / 32), dim3(32, 32)>>>(wt, wext, 3 * DM, DM);
        hmma_k<64, 0, 0, 1><<<dim3(DM / 64, ME / 128, 2), 256, HS64>>>(
            ime, wext, part, nullptr, 9 * DM, 9 * DM / 2, DM, MN, nullptr, nullptr, nullptr);
        combine_k<2, 0><<<(MN + 255) / 256, 256>>>(part, MN, DM, DM, h1, nullptr,
                                                   dp_c1b, dp_g1, dp_b1, nullptr);
        wt_k<<<(DM * DM * 3 + 255) / 256, 256>>>(dp_c2w, wt);
        im2col_k<<<(ME * DM * 3 + 255) / 256, 256>>>(h1, ime);
        split_w_k<<<dim3(DM / 32, 3 * DM / 32), dim3(32, 32)>>>(wt, wext, 3 * DM, DM);
        hmma_k<64, 0, 0, 1><<<dim3(DM / 64, ME / 128, 2), 256, HS64>>>(
            ime, wext, part, nullptr, 9 * DM, 9 * DM / 2, DM, MN, nullptr, nullptr, nullptr);
        combine_k<2, 0><<<(MN + 255) / 256, 256>>>(part, MN, DM, DM, h2, nullptr,
                                                   dp_c2b, dp_g2, dp_b2, nullptr);
        dur_k<<<(ME * 32 + 255) / 256, 256>>>(h2, dp_c3w, dp_c3b, dur);
    }

    expand_k<<<NB, TE>>>(dur, idx, mask);
    gather_k<<<(MD * DM + 255) / 256, 256>>>(x1, idx, mask, xe);

    mamba(x1, true, TD, 0, dec_in_w, dec_cw, dec_cb, dec_xpw, dec_dtw, dec_dtb, dec_alog, dec_dpv, dec_ow);
    mamba(x0, true, TD, 1, dec_in_w, dec_cw, dec_cb, dec_xpw, dec_dtw, dec_dtb, dec_alog, dec_dpv, dec_ow);
    mamba(x1, true, TD, 2, dec_in_w, dec_cw, dec_cb, dec_xpw, dec_dtw, dec_dtb, dec_alog, dec_dpv, dec_ow);

    // rmsnorm -> xe ext; mel = xe @ out_w (padded to 128 cols, split-K=2, masked combine)
    rmsnorm_k<<<MD, 128>>>(x1, norm_g, xe);
    {
        const int NPAD = 128;
        int MN = MD * NPAD;
        split_w_pad_k<<<dim3(NPAD / 32, DM / 32), dim3(32, 32)>>>(out_w, wext, DM, NM, NPAD);
        hmma_k<64, 0, 0, 1><<<dim3(NPAD / 64, MD / 128, 2), 256, HS64>>>(
            xe, wext, part, nullptr, 3 * DM, 3 * DM / 2, NPAD, MN, nullptr, nullptr, nullptr);
        combine_k<3, 0><<<(MN + 255) / 256, 256>>>(part, MN, NPAD, NM, (float*)d_out, nullptr,
                                                   nullptr, nullptr, nullptr, mask);
    }

    int melN = MD * NM;
    if (out_size > melN) {
        int n = out_size - melN;
        tail_k<<<(n + 255) / 256, 256>>>((float*)d_out + melN, mask, n);
    }
}